// round 1
// baseline (speedup 1.0000x reference)
#include <cuda_runtime.h>
#include <cstdint>
#include <math.h>

// Problem sizes (fixed)
#define BB   4
#define TT   1024
#define CC   512
#define HH   8
#define NN   64
#define BT   (BB*TT)        // 4096
#define BTC  (BT*CC)        // 2097152

// ---------------------------------------------------------------------------
// Workspace (static __device__ arrays; no allocation at runtime)
// ---------------------------------------------------------------------------
__device__ float g_xr[BTC], g_xw[BTC], g_xk[BTC], g_xv[BTC], g_xa[BTC], g_xg[BTC];
__device__ float g_gate[BT*HH];
__device__ float g_r[BTC], g_k[BTC], g_vraw[BTC];
__device__ float g_hw[BT*64], g_ha[BT*64], g_hv[BT*32], g_hg[BT*128];
__device__ float g_dec[BTC], g_a[BTC], g_v[BTC], g_g[BTC];
__device__ float g_kp[BTC], g_aa[BTC], g_bb[BTC];
__device__ float g_yf[BTC], g_yb[BTC], g_z[BTC];

// ---------------------------------------------------------------------------
// Kernel 1: token shift, six mixes, per-head gate
// grid = BT blocks, 128 threads; each thread owns 4 channels (float4)
// ---------------------------------------------------------------------------
__global__ void prep_kernel(const float* __restrict__ x,
                            const float* __restrict__ mr, const float* __restrict__ mw,
                            const float* __restrict__ mk, const float* __restrict__ mv,
                            const float* __restrict__ ma, const float* __restrict__ mg,
                            const float* __restrict__ gate_w)
{
    int bt = blockIdx.x;
    int t  = bt & (TT - 1);
    int tid = threadIdx.x;
    int c  = tid * 4;
    size_t base = (size_t)bt * CC + c;

    float4 xc = *(const float4*)(x + base);
    float4 xp = make_float4(0.f, 0.f, 0.f, 0.f);
    if (t != 0) xp = *(const float4*)(x + base - CC);

    float4 xx;
    xx.x = xp.x - xc.x; xx.y = xp.y - xc.y; xx.z = xp.z - xc.z; xx.w = xp.w - xc.w;

#define MIXOUT(dst, mvptr)                                                    \
    { float4 m = *(const float4*)(mvptr + c); float4 o;                       \
      o.x = xc.x + xx.x * m.x; o.y = xc.y + xx.y * m.y;                       \
      o.z = xc.z + xx.z * m.z; o.w = xc.w + xx.w * m.w;                       \
      *(float4*)(dst + base) = o; }
    MIXOUT(g_xr, mr); MIXOUT(g_xw, mw); MIXOUT(g_xk, mk);
    MIXOUT(g_xv, mv); MIXOUT(g_xa, ma); MIXOUT(g_xg, mg);
#undef MIXOUT

    // gate: sigmoid(sum_n xx[h,n]*gate_w[h,n]); gate_w flat index == channel
    float4 gw = *(const float4*)(gate_w + c);
    float p = xx.x*gw.x + xx.y*gw.y + xx.z*gw.z + xx.w*gw.w;
    #pragma unroll
    for (int o = 1; o < 16; o <<= 1) p += __shfl_xor_sync(0xffffffffu, p, o);
    if ((tid & 15) == 0)
        g_gate[bt*HH + (tid >> 4)] = 1.f / (1.f + expf(-p));
}

// ---------------------------------------------------------------------------
// Generic multi-job SGEMM: C[M,N] = A[M,K] @ op(B) with fused epilogues
// transb=1: B is [N,K] (K contiguous) -> C = A @ B^T
// transb=0: B is [K,N] (N contiguous) -> C = A @ B
// act: 0 none, 1 tanh, 2 sigmoid(+bias), 3 decay(+bias), 4 vmix(+bias,aux)
// ---------------------------------------------------------------------------
#define GBM 128
#define GBN 64
#define GBK 16

struct GemmJobs {
    int count;
    int tileStart[5];
    const float* A[4];
    const float* Bm[4];
    float*       Cm[4];
    int N[4];
    int K[4];
    int transb[4];
    int act[4];
    const float* bias[4];
    const float* aux1[4];
    const float* aux2[4];
};

__global__ __launch_bounds__(256, 2) void gemm_multi(GemmJobs J)
{
    __shared__ __align__(16) float As[GBM * 20];
    __shared__ float Bs[GBN * 21];

    int bx = blockIdx.x;
    int j = 0;
    while (bx >= J.tileStart[j + 1]) ++j;
    int n0 = (bx - J.tileStart[j]) * GBN;
    int m0 = blockIdx.y * GBM;

    const float* A = J.A[j];
    const float* B = J.Bm[j];
    float*       C = J.Cm[j];
    const int N = J.N[j];
    const int K = J.K[j];
    const int tb = J.transb[j];

    int tid = threadIdx.x;
    int tx = tid & 15, ty = tid >> 4;

    float acc[8][4];
    #pragma unroll
    for (int im = 0; im < 8; im++)
        #pragma unroll
        for (int in = 0; in < 4; in++) acc[im][in] = 0.f;

    for (int k0 = 0; k0 < K; k0 += GBK) {
        // load A tile (128x16), 2 float4 per thread
        #pragma unroll
        for (int it = 0; it < 2; it++) {
            int lid = tid + it * 256;
            int row = lid >> 2, kc = lid & 3;
            float4 v = *(const float4*)(A + (size_t)(m0 + row) * K + k0 + kc * 4);
            *(float4*)(As + row * 20 + kc * 4) = v;
        }
        // load B tile (64x16)
        if (tb) {
            int row = tid >> 2, kc = tid & 3;
            float4 v = *(const float4*)(B + (size_t)(n0 + row) * K + k0 + kc * 4);
            Bs[row * 21 + kc * 4 + 0] = v.x;
            Bs[row * 21 + kc * 4 + 1] = v.y;
            Bs[row * 21 + kc * 4 + 2] = v.z;
            Bs[row * 21 + kc * 4 + 3] = v.w;
        } else {
            int col = tid & 63, kq = tid >> 6;
            #pragma unroll
            for (int jj = 0; jj < 4; jj++) {
                int kr = k0 + kq * 4 + jj;
                float v = (n0 + col < N) ? B[(size_t)kr * N + n0 + col] : 0.f;
                Bs[col * 21 + kq * 4 + jj] = v;
            }
        }
        __syncthreads();

        #pragma unroll
        for (int kk = 0; kk < GBK; kk++) {
            float af[8], bf[4];
            #pragma unroll
            for (int im = 0; im < 8; im++) af[im] = As[(ty * 8 + im) * 20 + kk];
            #pragma unroll
            for (int in = 0; in < 4; in++) bf[in] = Bs[(tx * 4 + in) * 21 + kk];
            #pragma unroll
            for (int im = 0; im < 8; im++)
                #pragma unroll
                for (int in = 0; in < 4; in++) acc[im][in] += af[im] * bf[in];
        }
        __syncthreads();
    }

    const int act = J.act[j];
    const float* bias = J.bias[j];
    const float* aux1 = J.aux1[j];
    const float* aux2 = J.aux2[j];

    #pragma unroll
    for (int im = 0; im < 8; im++) {
        int row = m0 + ty * 8 + im;
        #pragma unroll
        for (int in = 0; in < 4; in++) {
            int col = n0 + tx * 4 + in;
            if (col < N) {
                size_t idx = (size_t)row * N + col;
                float v = acc[im][in];
                float o;
                if (act == 0) {
                    o = v;
                } else if (act == 1) {
                    o = tanhf(v);
                } else if (act == 2) {
                    float z = v + (bias ? bias[col] : 0.f);
                    o = 1.f / (1.f + expf(-z));
                } else if (act == 3) {
                    // w = -softplus(-z)-0.5; dec = exp(-exp(w)) = exp(-e^{-0.5} * sigmoid(z))
                    float z = v + bias[col];
                    float s = 1.f / (1.f + expf(-z));
                    o = expf(-0.60653065971263342f * s);
                } else {
                    float z = v + bias[col];
                    float s = 1.f / (1.f + expf(-z));
                    float vr = aux1[idx];
                    o = vr + (aux2[idx] - vr) * s;
                }
                C[idx] = o;
            }
        }
    }
}

// ---------------------------------------------------------------------------
// Kernel: post — kk normalization per head, k' update, aa=-kk, bb=kk*a
// grid = BT, 128 threads
// ---------------------------------------------------------------------------
__global__ void post_kernel(const float* __restrict__ k_k, const float* __restrict__ k_a)
{
    int bt = blockIdx.x;
    int tid = threadIdx.x;
    int c = tid * 4;
    size_t base = (size_t)bt * CC + c;

    float4 kv = *(const float4*)(g_k + base);
    float4 av = *(const float4*)(g_a + base);
    float4 kkc = *(const float4*)(k_k + c);
    float4 kac = *(const float4*)(k_a + c);

    float4 kk;
    kk.x = kv.x * kkc.x; kk.y = kv.y * kkc.y; kk.z = kv.z * kkc.z; kk.w = kv.w * kkc.w;
    float ss = kk.x*kk.x + kk.y*kk.y + kk.z*kk.z + kk.w*kk.w;
    #pragma unroll
    for (int o = 1; o < 16; o <<= 1) ss += __shfl_xor_sync(0xffffffffu, ss, o);

    float nrm = sqrtf(ss);
    float inv = 1.f / fmaxf(nrm, 1e-12f);

    float4 aa, bb, kp;
    aa.x = -kk.x * inv; aa.y = -kk.y * inv; aa.z = -kk.z * inv; aa.w = -kk.w * inv;
    bb.x = kk.x * inv * av.x; bb.y = kk.y * inv * av.y;
    bb.z = kk.z * inv * av.z; bb.w = kk.w * inv * av.w;
    kp.x = kv.x * (1.f + (av.x - 1.f) * kac.x);
    kp.y = kv.y * (1.f + (av.y - 1.f) * kac.y);
    kp.z = kv.z * (1.f + (av.z - 1.f) * kac.z);
    kp.w = kv.w * (1.f + (av.w - 1.f) * kac.w);

    *(float4*)(g_aa + base) = aa;
    *(float4*)(g_bb + base) = bb;
    *(float4*)(g_kp + base) = kp;
}

// ---------------------------------------------------------------------------
// Kernel: bidirectional WKV7 scan.
// grid = 64 (dir*32 + b*8 + h), 256 threads.
// thread (i = tid>>2, q = tid&3) owns state row i, cols [q*16, q*16+16).
// Per-step operands staged in shared, double buffered, prefetched 1 ahead.
// ---------------------------------------------------------------------------
__global__ __launch_bounds__(256, 1) void scan_kernel()
{
    int bx = blockIdx.x;
    int dir = bx >> 5;
    int b = (bx >> 3) & 3;
    int h = bx & 7;
    int tid = threadIdx.x;
    int i = tid >> 2, q = tid & 3;
    int c0 = q * 16;

    __shared__ __align__(16) float buf[2][384];  // r|dec|kp|v|aa|bb each 64

    bool loader = tid < 96;
    int arr = tid >> 4, l16 = tid & 15;
    const float* sp = nullptr;
    if (loader) {
        switch (arr) {
            case 0: sp = g_r;   break;
            case 1: sp = g_dec; break;
            case 2: sp = g_kp;  break;
            case 3: sp = g_v;   break;
            case 4: sp = g_aa;  break;
            default: sp = g_bb; break;
        }
    }
    int t0 = dir ? (TT - 1) : 0;
    int stride = dir ? -CC : CC;
    const float* lp = nullptr;
    float4 pre = make_float4(0.f, 0.f, 0.f, 0.f);
    if (loader) {
        lp = sp + (size_t)(b * TT + t0) * CC + h * NN + l16 * 4;
        pre = *(const float4*)lp;
        *(float4*)&buf[0][arr * 64 + l16 * 4] = pre;
    }
    __syncthreads();

    float S[16];
    #pragma unroll
    for (int jj = 0; jj < 16; jj++) S[jj] = 0.f;

    float* yout = dir ? g_yb : g_yf;
    int t = t0;

    for (int s = 0; s < TT; s++) {
        int cur = s & 1;
        if (loader && s + 1 < TT) { lp += stride; pre = *(const float4*)lp; }

        const float* bc = buf[cur];
        // sa_i = sum_j S[i][j] * aa[j]
        float sa = 0.f;
        #pragma unroll
        for (int jj = 0; jj < 4; jj++) {
            float4 av = *(const float4*)(bc + 256 + c0 + jj * 4);
            sa += S[jj*4+0]*av.x + S[jj*4+1]*av.y + S[jj*4+2]*av.z + S[jj*4+3]*av.w;
        }
        sa += __shfl_xor_sync(0xffffffffu, sa, 1);
        sa += __shfl_xor_sync(0xffffffffu, sa, 2);

        float vi = bc[192 + i];
        float y = 0.f;
        #pragma unroll
        for (int jj = 0; jj < 4; jj++) {
            float4 dv = *(const float4*)(bc + 64  + c0 + jj * 4);
            float4 bv = *(const float4*)(bc + 320 + c0 + jj * 4);
            float4 kv = *(const float4*)(bc + 128 + c0 + jj * 4);
            float4 rv = *(const float4*)(bc + 0   + c0 + jj * 4);
            float s0;
            s0 = S[jj*4+0]*dv.x + sa*bv.x + vi*kv.x; S[jj*4+0] = s0; y += s0*rv.x;
            s0 = S[jj*4+1]*dv.y + sa*bv.y + vi*kv.y; S[jj*4+1] = s0; y += s0*rv.y;
            s0 = S[jj*4+2]*dv.z + sa*bv.z + vi*kv.z; S[jj*4+2] = s0; y += s0*rv.z;
            s0 = S[jj*4+3]*dv.w + sa*bv.w + vi*kv.w; S[jj*4+3] = s0; y += s0*rv.w;
        }
        y += __shfl_xor_sync(0xffffffffu, y, 1);
        y += __shfl_xor_sync(0xffffffffu, y, 2);
        if (q == 0)
            yout[(size_t)(b * TT + t) * CC + h * NN + i] = y;

        if (loader && s + 1 < TT)
            *(float4*)&buf[cur ^ 1][arr * 64 + l16 * 4] = pre;
        __syncthreads();
        t += dir ? -1 : 1;
    }
}

// ---------------------------------------------------------------------------
// Kernel: combine — gate-mix fwd/bwd, groupnorm, residual, * g
// grid = BT, 128 threads
// ---------------------------------------------------------------------------
__global__ void combine_kernel(const float* __restrict__ r_k,
                               const float* __restrict__ ln_g,
                               const float* __restrict__ ln_b)
{
    int bt = blockIdx.x;
    int tid = threadIdx.x;
    int c = tid * 4;
    int h = tid >> 4;
    size_t base = (size_t)bt * CC + c;

    float4 yf = *(const float4*)(g_yf + base);
    float4 yb = *(const float4*)(g_yb + base);
    float gate = g_gate[bt * HH + h];

    float4 xo;
    xo.x = gate * yf.x + (1.f - gate) * yb.x;
    xo.y = gate * yf.y + (1.f - gate) * yb.y;
    xo.z = gate * yf.z + (1.f - gate) * yb.z;
    xo.w = gate * yf.w + (1.f - gate) * yb.w;

    float4 rv = *(const float4*)(g_r + base);
    float4 kp = *(const float4*)(g_kp + base);
    float4 vv = *(const float4*)(g_v + base);
    float4 gv = *(const float4*)(g_g + base);
    float4 rk = *(const float4*)(r_k + c);

    float sum = xo.x + xo.y + xo.z + xo.w;
    float sq  = xo.x*xo.x + xo.y*xo.y + xo.z*xo.z + xo.w*xo.w;
    float sres = rv.x*kp.x*rk.x + rv.y*kp.y*rk.y + rv.z*kp.z*rk.z + rv.w*kp.w*rk.w;
    #pragma unroll
    for (int o = 1; o < 16; o <<= 1) {
        sum  += __shfl_xor_sync(0xffffffffu, sum, o);
        sq   += __shfl_xor_sync(0xffffffffu, sq, o);
        sres += __shfl_xor_sync(0xffffffffu, sres, o);
    }
    float mu = sum * (1.f / 64.f);
    float var = sq * (1.f / 64.f) - mu * mu;
    float rstd = rsqrtf(var + 0.00064f);

    float4 lg = *(const float4*)(ln_g + c);
    float4 lb = *(const float4*)(ln_b + c);

    float4 z;
    z.x = ((xo.x - mu) * rstd * lg.x + lb.x + sres * vv.x) * gv.x;
    z.y = ((xo.y - mu) * rstd * lg.y + lb.y + sres * vv.y) * gv.y;
    z.z = ((xo.z - mu) * rstd * lg.z + lb.z + sres * vv.z) * gv.z;
    z.w = ((xo.w - mu) * rstd * lg.w + lb.w + sres * vv.w) * gv.w;
    *(float4*)(g_z + base) = z;
}

// ---------------------------------------------------------------------------
// Host launcher
// ---------------------------------------------------------------------------
static float *P_xr, *P_xw, *P_xk, *P_xv, *P_xa, *P_xg;
static float *P_r, *P_k, *P_vraw;
static float *P_hw, *P_ha, *P_hv, *P_hg;
static float *P_dec, *P_a, *P_v, *P_g;
static float *P_z;
static bool s_init = false;

extern "C" void kernel_launch(void* const* d_in, const int* in_sizes, int n_in,
                              void* d_out, int out_size)
{
    const float* x       = (const float*)d_in[0];
    const float* v_first = (const float*)d_in[1];
    const float* x_r = (const float*)d_in[2];
    const float* x_w = (const float*)d_in[3];
    const float* x_k = (const float*)d_in[4];
    const float* x_v = (const float*)d_in[5];
    const float* x_a = (const float*)d_in[6];
    const float* x_g = (const float*)d_in[7];
    const float* w0  = (const float*)d_in[8];
    const float* w1  = (const float*)d_in[9];
    const float* w2  = (const float*)d_in[10];
    const float* a0  = (const float*)d_in[11];
    const float* a1  = (const float*)d_in[12];
    const float* a2  = (const float*)d_in[13];
    const float* v0  = (const float*)d_in[14];
    const float* v1  = (const float*)d_in[15];
    const float* v2  = (const float*)d_in[16];
    const float* g1  = (const float*)d_in[17];
    const float* g2  = (const float*)d_in[18];
    const float* k_k = (const float*)d_in[19];
    const float* k_a = (const float*)d_in[20];
    const float* r_k = (const float*)d_in[21];
    const float* gate_w = (const float*)d_in[22];
    const float* ln_g = (const float*)d_in[23];
    const float* ln_b = (const float*)d_in[24];
    const float* Wr = (const float*)d_in[25];
    const float* Wk = (const float*)d_in[26];
    const float* Wv = (const float*)d_in[27];
    const float* Wo = (const float*)d_in[28];
    float* out = (float*)d_out;

    if (!s_init) {
        cudaGetSymbolAddress((void**)&P_xr, g_xr);
        cudaGetSymbolAddress((void**)&P_xw, g_xw);
        cudaGetSymbolAddress((void**)&P_xk, g_xk);
        cudaGetSymbolAddress((void**)&P_xv, g_xv);
        cudaGetSymbolAddress((void**)&P_xa, g_xa);
        cudaGetSymbolAddress((void**)&P_xg, g_xg);
        cudaGetSymbolAddress((void**)&P_r, g_r);
        cudaGetSymbolAddress((void**)&P_k, g_k);
        cudaGetSymbolAddress((void**)&P_vraw, g_vraw);
        cudaGetSymbolAddress((void**)&P_hw, g_hw);
        cudaGetSymbolAddress((void**)&P_ha, g_ha);
        cudaGetSymbolAddress((void**)&P_hv, g_hv);
        cudaGetSymbolAddress((void**)&P_hg, g_hg);
        cudaGetSymbolAddress((void**)&P_dec, g_dec);
        cudaGetSymbolAddress((void**)&P_a, g_a);
        cudaGetSymbolAddress((void**)&P_v, g_v);
        cudaGetSymbolAddress((void**)&P_g, g_g);
        cudaGetSymbolAddress((void**)&P_z, g_z);
        s_init = true;
    }

    // 1) token shift + mixes + gate
    prep_kernel<<<BT, 128>>>(x, x_r, x_w, x_k, x_v, x_a, x_g, gate_w);

    // 2) big QKV GEMMs (A @ W^T), one launch
    {
        GemmJobs J = {};
        J.count = 3;
        J.tileStart[0] = 0; J.tileStart[1] = 8; J.tileStart[2] = 16; J.tileStart[3] = 24; J.tileStart[4] = 24;
        const float* As_[3] = { P_xr, P_xk, P_xv };
        const float* Bs_[3] = { Wr, Wk, Wv };
        float* Cs_[3] = { P_r, P_k, P_vraw };
        for (int jj = 0; jj < 3; jj++) {
            J.A[jj] = As_[jj]; J.Bm[jj] = Bs_[jj]; J.Cm[jj] = Cs_[jj];
            J.N[jj] = 512; J.K[jj] = 512; J.transb[jj] = 1; J.act[jj] = 0;
            J.bias[jj] = nullptr; J.aux1[jj] = nullptr; J.aux2[jj] = nullptr;
        }
        gemm_multi<<<dim3(24, 32), 256>>>(J);
    }

    // 3) stage-1 hidden GEMMs (A @ B), one launch
    {
        GemmJobs J = {};
        J.count = 4;
        J.tileStart[0] = 0; J.tileStart[1] = 1; J.tileStart[2] = 2; J.tileStart[3] = 3; J.tileStart[4] = 5;
        // w-hidden: tanh(xw @ w1)
        J.A[0] = P_xw; J.Bm[0] = w1; J.Cm[0] = P_hw; J.N[0] = 64;  J.K[0] = 512; J.transb[0] = 0; J.act[0] = 1;
        // a-hidden: xa @ a1
        J.A[1] = P_xa; J.Bm[1] = a1; J.Cm[1] = P_ha; J.N[1] = 64;  J.K[1] = 512; J.transb[1] = 0; J.act[1] = 0;
        // v-hidden: x @ v1
        J.A[2] = x;    J.Bm[2] = v1; J.Cm[2] = P_hv; J.N[2] = 32;  J.K[2] = 512; J.transb[2] = 0; J.act[2] = 0;
        // g-hidden: sigmoid(xg @ g1)
        J.A[3] = P_xg; J.Bm[3] = g1; J.Cm[3] = P_hg; J.N[3] = 128; J.K[3] = 512; J.transb[3] = 0; J.act[3] = 2;
        for (int jj = 0; jj < 4; jj++) { J.bias[jj] = nullptr; J.aux1[jj] = nullptr; J.aux2[jj] = nullptr; }
        gemm_multi<<<dim3(5, 32), 256>>>(J);
    }

    // 4) stage-2 GEMMs with fused epilogues, one launch
    {
        GemmJobs J = {};
        J.count = 4;
        J.tileStart[0] = 0; J.tileStart[1] = 8; J.tileStart[2] = 16; J.tileStart[3] = 24; J.tileStart[4] = 32;
        // dec = exp(-exp(w)), w from hw @ w2 + w0
        J.A[0] = P_hw; J.Bm[0] = w2; J.Cm[0] = P_dec; J.N[0] = 512; J.K[0] = 64;  J.transb[0] = 0; J.act[0] = 3;
        J.bias[0] = w0; J.aux1[0] = nullptr; J.aux2[0] = nullptr;
        // a = sigmoid(a0 + ha @ a2)
        J.A[1] = P_ha; J.Bm[1] = a2; J.Cm[1] = P_a; J.N[1] = 512; J.K[1] = 64;  J.transb[1] = 0; J.act[1] = 2;
        J.bias[1] = a0; J.aux1[1] = nullptr; J.aux2[1] = nullptr;
        // v = vraw + (v_first - vraw) * sigmoid(v0 + hv @ v2)
        J.A[2] = P_hv; J.Bm[2] = v2; J.Cm[2] = P_v; J.N[2] = 512; J.K[2] = 32;  J.transb[2] = 0; J.act[2] = 4;
        J.bias[2] = v0; J.aux1[2] = P_vraw; J.aux2[2] = v_first;
        // g = hg_sig @ g2
        J.A[3] = P_hg; J.Bm[3] = g2; J.Cm[3] = P_g; J.N[3] = 512; J.K[3] = 128; J.transb[3] = 0; J.act[3] = 0;
        J.bias[3] = nullptr; J.aux1[3] = nullptr; J.aux2[3] = nullptr;
        gemm_multi<<<dim3(32, 32), 256>>>(J);
    }

    // 5) kk normalize, k', aa, bb
    post_kernel<<<BT, 128>>>(k_k, k_a);

    // 6) bidirectional WKV7 scan
    scan_kernel<<<64, 256>>>();

    // 7) combine + groupnorm + residual + *g
    combine_kernel<<<BT, 128>>>(r_k, ln_g, ln_b);

    // 8) out = z @ Wo^T
    {
        GemmJobs J = {};
        J.count = 1;
        J.tileStart[0] = 0; J.tileStart[1] = 8; J.tileStart[2] = 8; J.tileStart[3] = 8; J.tileStart[4] = 8;
        J.A[0] = P_z; J.Bm[0] = Wo; J.Cm[0] = out;
        J.N[0] = 512; J.K[0] = 512; J.transb[0] = 1; J.act[0] = 0;
        J.bias[0] = nullptr; J.aux1[0] = nullptr; J.aux2[0] = nullptr;
        gemm_multi<<<dim3(8, 32), 256>>>(J);
    }

    // 9) v_first passthrough if the flattened output includes it
    if (out_size >= 2 * BTC) {
        cudaMemcpyAsync(out + BTC, v_first, (size_t)BTC * sizeof(float),
                        cudaMemcpyDeviceToDevice, 0);
    }
}

// round 2
// speedup vs baseline: 1.1640x; 1.1640x over previous
#include <cuda_runtime.h>
#include <cstdint>
#include <math.h>

// Problem sizes (fixed)
#define BB   4
#define TT   1024
#define CC   512
#define HH   8
#define NN   64
#define BT   (BB*TT)        // 4096
#define BTC  (BT*CC)        // 2097152

// ---------------------------------------------------------------------------
// Workspace (static __device__ arrays; no allocation at runtime)
// ---------------------------------------------------------------------------
__device__ float g_xr[BTC], g_xw[BTC], g_xk[BTC], g_xv[BTC], g_xa[BTC], g_xg[BTC];
__device__ float g_gate[BT*HH];
__device__ float g_r[BTC], g_k[BTC], g_vraw[BTC];
__device__ float g_hw[BT*64], g_ha[BT*64], g_hv[BT*32], g_hg[BT*128];
__device__ float g_dec[BTC], g_a[BTC], g_v[BTC], g_g[BTC];
__device__ float g_kp[BTC], g_aa[BTC], g_bb[BTC];
__device__ float g_yf[BTC], g_yb[BTC], g_z[BTC];

// ---------------------------------------------------------------------------
// Kernel 1: token shift, six mixes, per-head gate
// ---------------------------------------------------------------------------
__global__ void prep_kernel(const float* __restrict__ x,
                            const float* __restrict__ mr, const float* __restrict__ mw,
                            const float* __restrict__ mk, const float* __restrict__ mv,
                            const float* __restrict__ ma, const float* __restrict__ mg,
                            const float* __restrict__ gate_w)
{
    int bt = blockIdx.x;
    int t  = bt & (TT - 1);
    int tid = threadIdx.x;
    int c  = tid * 4;
    size_t base = (size_t)bt * CC + c;

    float4 xc = *(const float4*)(x + base);
    float4 xp = make_float4(0.f, 0.f, 0.f, 0.f);
    if (t != 0) xp = *(const float4*)(x + base - CC);

    float4 xx;
    xx.x = xp.x - xc.x; xx.y = xp.y - xc.y; xx.z = xp.z - xc.z; xx.w = xp.w - xc.w;

#define MIXOUT(dst, mvptr)                                                    \
    { float4 m = *(const float4*)(mvptr + c); float4 o;                       \
      o.x = xc.x + xx.x * m.x; o.y = xc.y + xx.y * m.y;                       \
      o.z = xc.z + xx.z * m.z; o.w = xc.w + xx.w * m.w;                       \
      *(float4*)(dst + base) = o; }
    MIXOUT(g_xr, mr); MIXOUT(g_xw, mw); MIXOUT(g_xk, mk);
    MIXOUT(g_xv, mv); MIXOUT(g_xa, ma); MIXOUT(g_xg, mg);
#undef MIXOUT

    float4 gw = *(const float4*)(gate_w + c);
    float p = xx.x*gw.x + xx.y*gw.y + xx.z*gw.z + xx.w*gw.w;
    #pragma unroll
    for (int o = 1; o < 16; o <<= 1) p += __shfl_xor_sync(0xffffffffu, p, o);
    if ((tid & 15) == 0)
        g_gate[bt*HH + (tid >> 4)] = 1.f / (1.f + expf(-p));
}

// ---------------------------------------------------------------------------
// Generic multi-job SGEMM with transposed smem tiles for vector LDS.
// transb=1: B is [N,K] -> C = A @ B^T ; transb=0: B is [K,N] -> C = A @ B
// act: 0 none, 1 tanh, 2 sigmoid(+bias), 3 decay(+bias), 4 vmix(+bias,aux)
// ---------------------------------------------------------------------------
#define GBM 128
#define GBN 64
#define GBK 16

struct GemmJobs {
    int count;
    int tileStart[5];
    const float* A[4];
    const float* Bm[4];
    float*       Cm[4];
    int N[4];
    int K[4];
    int transb[4];
    int act[4];
    const float* bias[4];
    const float* aux1[4];
    const float* aux2[4];
};

__global__ __launch_bounds__(256, 2) void gemm_multi(GemmJobs J)
{
    __shared__ __align__(16) float As[GBK][GBM + 4];   // [k][m]
    __shared__ __align__(16) float Bs[GBK][GBN + 4];   // [k][n]

    int bx = blockIdx.x;
    int j = 0;
    while (bx >= J.tileStart[j + 1]) ++j;
    int n0 = (bx - J.tileStart[j]) * GBN;
    int m0 = blockIdx.y * GBM;

    const float* A = J.A[j];
    const float* B = J.Bm[j];
    float*       C = J.Cm[j];
    const int N = J.N[j];
    const int K = J.K[j];
    const int tb = J.transb[j];

    int tid = threadIdx.x;
    int tx = tid & 15, ty = tid >> 4;

    float acc[8][4];
    #pragma unroll
    for (int im = 0; im < 8; im++)
        #pragma unroll
        for (int in = 0; in < 4; in++) acc[im][in] = 0.f;

    for (int k0 = 0; k0 < K; k0 += GBK) {
        // A tile (128 rows x 16 k), transposed into As[k][m]
        #pragma unroll
        for (int it = 0; it < 2; it++) {
            int lid = tid + it * 256;
            int row = lid >> 2, kc = lid & 3;
            float4 v = *(const float4*)(A + (size_t)(m0 + row) * K + k0 + kc * 4);
            As[kc*4+0][row] = v.x;
            As[kc*4+1][row] = v.y;
            As[kc*4+2][row] = v.z;
            As[kc*4+3][row] = v.w;
        }
        // B tile into Bs[k][n]
        if (tb) {
            int row = tid >> 2, kc = tid & 3;
            float4 v = *(const float4*)(B + (size_t)(n0 + row) * K + k0 + kc * 4);
            Bs[kc*4+0][row] = v.x;
            Bs[kc*4+1][row] = v.y;
            Bs[kc*4+2][row] = v.z;
            Bs[kc*4+3][row] = v.w;
        } else {
            int kr = tid >> 4, c4 = (tid & 15) * 4;
            float4 v = make_float4(0.f, 0.f, 0.f, 0.f);
            if (n0 + c4 < N)
                v = *(const float4*)(B + (size_t)(k0 + kr) * N + n0 + c4);
            *(float4*)&Bs[kr][c4] = v;
        }
        __syncthreads();

        #pragma unroll
        for (int kk = 0; kk < GBK; kk++) {
            float4 bf = *(const float4*)&Bs[kk][tx * 4];
            float4 a0 = *(const float4*)&As[kk][ty * 8];
            float4 a1 = *(const float4*)&As[kk][ty * 8 + 4];
            float af[8] = {a0.x, a0.y, a0.z, a0.w, a1.x, a1.y, a1.z, a1.w};
            float bb2[4] = {bf.x, bf.y, bf.z, bf.w};
            #pragma unroll
            for (int im = 0; im < 8; im++)
                #pragma unroll
                for (int in = 0; in < 4; in++) acc[im][in] += af[im] * bb2[in];
        }
        __syncthreads();
    }

    const int act = J.act[j];
    const float* bias = J.bias[j];
    const float* aux1 = J.aux1[j];
    const float* aux2 = J.aux2[j];

    #pragma unroll
    for (int im = 0; im < 8; im++) {
        int row = m0 + ty * 8 + im;
        #pragma unroll
        for (int in = 0; in < 4; in++) {
            int col = n0 + tx * 4 + in;
            if (col < N) {
                size_t idx = (size_t)row * N + col;
                float v = acc[im][in];
                float o;
                if (act == 0) {
                    o = v;
                } else if (act == 1) {
                    o = tanhf(v);
                } else if (act == 2) {
                    float z = v + (bias ? bias[col] : 0.f);
                    o = 1.f / (1.f + expf(-z));
                } else if (act == 3) {
                    float z = v + bias[col];
                    float s = 1.f / (1.f + expf(-z));
                    o = expf(-0.60653065971263342f * s);
                } else {
                    float z = v + bias[col];
                    float s = 1.f / (1.f + expf(-z));
                    float vr = aux1[idx];
                    o = vr + (aux2[idx] - vr) * s;
                }
                C[idx] = o;
            }
        }
    }
}

// ---------------------------------------------------------------------------
// Kernel: post — kk normalization per head, k' update, aa=-kk, bb=kk*a
// ---------------------------------------------------------------------------
__global__ void post_kernel(const float* __restrict__ k_k, const float* __restrict__ k_a)
{
    int bt = blockIdx.x;
    int tid = threadIdx.x;
    int c = tid * 4;
    size_t base = (size_t)bt * CC + c;

    float4 kv = *(const float4*)(g_k + base);
    float4 av = *(const float4*)(g_a + base);
    float4 kkc = *(const float4*)(k_k + c);
    float4 kac = *(const float4*)(k_a + c);

    float4 kk;
    kk.x = kv.x * kkc.x; kk.y = kv.y * kkc.y; kk.z = kv.z * kkc.z; kk.w = kv.w * kkc.w;
    float ss = kk.x*kk.x + kk.y*kk.y + kk.z*kk.z + kk.w*kk.w;
    #pragma unroll
    for (int o = 1; o < 16; o <<= 1) ss += __shfl_xor_sync(0xffffffffu, ss, o);

    float nrm = sqrtf(ss);
    float inv = 1.f / fmaxf(nrm, 1e-12f);

    float4 aa, bb, kp;
    aa.x = -kk.x * inv; aa.y = -kk.y * inv; aa.z = -kk.z * inv; aa.w = -kk.w * inv;
    bb.x = kk.x * inv * av.x; bb.y = kk.y * inv * av.y;
    bb.z = kk.z * inv * av.z; bb.w = kk.w * inv * av.w;
    kp.x = kv.x * (1.f + (av.x - 1.f) * kac.x);
    kp.y = kv.y * (1.f + (av.y - 1.f) * kac.y);
    kp.z = kv.z * (1.f + (av.z - 1.f) * kac.z);
    kp.w = kv.w * (1.f + (av.w - 1.f) * kac.w);

    *(float4*)(g_aa + base) = aa;
    *(float4*)(g_bb + base) = bb;
    *(float4*)(g_kp + base) = kp;
}

// ---------------------------------------------------------------------------
// Kernel: bidirectional WKV7 scan — barrier-free, register-resident.
// grid = 128 blocks (dir*64 + b*16 + h*2 + rowgroup), 128 threads.
// thread (i = rg*32 + tid>>2, q = tid&3) owns row i, cols [q*16, q*16+16).
// Operands loaded per-thread via LDG, single-buffered with staggered reload.
// Only 2+2 shuffles per step; zero barriers.
// ---------------------------------------------------------------------------
__global__ __launch_bounds__(128, 4) void scan_kernel()
{
    int bx = blockIdx.x;
    int dir = bx >> 6;
    int b   = (bx >> 4) & 3;
    int h   = (bx >> 1) & 7;
    int rg  = bx & 1;
    int tid = threadIdx.x;
    int i   = rg * 32 + (tid >> 2);
    int q   = tid & 3;
    int c0  = q * 16;

    int t0 = dir ? (TT - 1) : 0;
    int stride = dir ? -CC : CC;
    size_t off = (size_t)(b * TT + t0) * CC + h * NN;

    const float* pr = g_r   + off + c0;
    const float* pd = g_dec + off + c0;
    const float* pk = g_kp  + off + c0;
    const float* pa = g_aa  + off + c0;
    const float* pb = g_bb  + off + c0;
    const float* pv = g_v   + off + i;
    float* py = (dir ? g_yb : g_yf) + off + i;

    float S[16];
    #pragma unroll
    for (int j = 0; j < 16; j++) S[j] = 0.f;

    float Rr[16], Dd[16], Kk[16], Aa[16], Bb[16], V;
    #pragma unroll
    for (int u = 0; u < 4; u++) {
        *(float4*)&Rr[u*4] = *(const float4*)(pr + u*4);
        *(float4*)&Dd[u*4] = *(const float4*)(pd + u*4);
        *(float4*)&Kk[u*4] = *(const float4*)(pk + u*4);
        *(float4*)&Aa[u*4] = *(const float4*)(pa + u*4);
        *(float4*)&Bb[u*4] = *(const float4*)(pb + u*4);
    }
    V = *pv;

    for (int s = 0; s < TT; s++) {
        // sa partial (4 independent chains)
        float p0 = S[0]*Aa[0]  + S[1]*Aa[1]   + S[2]*Aa[2]   + S[3]*Aa[3];
        float p1 = S[4]*Aa[4]  + S[5]*Aa[5]   + S[6]*Aa[6]   + S[7]*Aa[7];
        float p2 = S[8]*Aa[8]  + S[9]*Aa[9]   + S[10]*Aa[10] + S[11]*Aa[11];
        float p3 = S[12]*Aa[12]+ S[13]*Aa[13] + S[14]*Aa[14] + S[15]*Aa[15];
        float sa = (p0 + p1) + (p2 + p3);

        bool more = (s + 1 < TT);
        // Aa done: reload for next step (covers L2 latency with rest of step)
        pa += stride;
        if (more) {
            #pragma unroll
            for (int u = 0; u < 4; u++)
                *(float4*)&Aa[u*4] = *(const float4*)(pa + u*4);
        }

        sa += __shfl_xor_sync(0xffffffffu, sa, 1);
        sa += __shfl_xor_sync(0xffffffffu, sa, 2);

        float y0 = 0.f, y1 = 0.f, y2 = 0.f, y3 = 0.f;
        #pragma unroll
        for (int j = 0; j < 4; j++) {
            float sj;
            sj = S[j]*Dd[j] + sa*Bb[j] + V*Kk[j];       S[j]    = sj; y0 += sj*Rr[j];
            sj = S[4+j]*Dd[4+j] + sa*Bb[4+j] + V*Kk[4+j];   S[4+j]  = sj; y1 += sj*Rr[4+j];
            sj = S[8+j]*Dd[8+j] + sa*Bb[8+j] + V*Kk[8+j];   S[8+j]  = sj; y2 += sj*Rr[8+j];
            sj = S[12+j]*Dd[12+j] + sa*Bb[12+j] + V*Kk[12+j]; S[12+j] = sj; y3 += sj*Rr[12+j];
        }
        float y = (y0 + y1) + (y2 + y3);

        // operands consumed: reload for next step
        pr += stride; pd += stride; pk += stride; pb += stride; pv += stride;
        if (more) {
            #pragma unroll
            for (int u = 0; u < 4; u++) {
                *(float4*)&Rr[u*4] = *(const float4*)(pr + u*4);
                *(float4*)&Dd[u*4] = *(const float4*)(pd + u*4);
                *(float4*)&Kk[u*4] = *(const float4*)(pk + u*4);
                *(float4*)&Bb[u*4] = *(const float4*)(pb + u*4);
            }
            V = *pv;
        }

        y += __shfl_xor_sync(0xffffffffu, y, 1);
        y += __shfl_xor_sync(0xffffffffu, y, 2);
        if (q == 0) *py = y;
        py += stride;
    }
}

// ---------------------------------------------------------------------------
// Kernel: combine — gate-mix fwd/bwd, groupnorm, residual, * g
// ---------------------------------------------------------------------------
__global__ void combine_kernel(const float* __restrict__ r_k,
                               const float* __restrict__ ln_g,
                               const float* __restrict__ ln_b)
{
    int bt = blockIdx.x;
    int tid = threadIdx.x;
    int c = tid * 4;
    int h = tid >> 4;
    size_t base = (size_t)bt * CC + c;

    float4 yf = *(const float4*)(g_yf + base);
    float4 yb = *(const float4*)(g_yb + base);
    float gate = g_gate[bt * HH + h];

    float4 xo;
    xo.x = gate * yf.x + (1.f - gate) * yb.x;
    xo.y = gate * yf.y + (1.f - gate) * yb.y;
    xo.z = gate * yf.z + (1.f - gate) * yb.z;
    xo.w = gate * yf.w + (1.f - gate) * yb.w;

    float4 rv = *(const float4*)(g_r + base);
    float4 kp = *(const float4*)(g_kp + base);
    float4 vv = *(const float4*)(g_v + base);
    float4 gv = *(const float4*)(g_g + base);
    float4 rk = *(const float4*)(r_k + c);

    float sum = xo.x + xo.y + xo.z + xo.w;
    float sq  = xo.x*xo.x + xo.y*xo.y + xo.z*xo.z + xo.w*xo.w;
    float sres = rv.x*kp.x*rk.x + rv.y*kp.y*rk.y + rv.z*kp.z*rk.z + rv.w*kp.w*rk.w;
    #pragma unroll
    for (int o = 1; o < 16; o <<= 1) {
        sum  += __shfl_xor_sync(0xffffffffu, sum, o);
        sq   += __shfl_xor_sync(0xffffffffu, sq, o);
        sres += __shfl_xor_sync(0xffffffffu, sres, o);
    }
    float mu = sum * (1.f / 64.f);
    float var = sq * (1.f / 64.f) - mu * mu;
    float rstd = rsqrtf(var + 0.00064f);

    float4 lg = *(const float4*)(ln_g + c);
    float4 lb = *(const float4*)(ln_b + c);

    float4 z;
    z.x = ((xo.x - mu) * rstd * lg.x + lb.x + sres * vv.x) * gv.x;
    z.y = ((xo.y - mu) * rstd * lg.y + lb.y + sres * vv.y) * gv.y;
    z.z = ((xo.z - mu) * rstd * lg.z + lb.z + sres * vv.z) * gv.z;
    z.w = ((xo.w - mu) * rstd * lg.w + lb.w + sres * vv.w) * gv.w;
    *(float4*)(g_z + base) = z;
}

// ---------------------------------------------------------------------------
// Host launcher
// ---------------------------------------------------------------------------
static float *P_xr, *P_xw, *P_xk, *P_xv, *P_xa, *P_xg;
static float *P_r, *P_k, *P_vraw;
static float *P_hw, *P_ha, *P_hv, *P_hg;
static float *P_dec, *P_a, *P_v, *P_g;
static float *P_z;
static bool s_init = false;

extern "C" void kernel_launch(void* const* d_in, const int* in_sizes, int n_in,
                              void* d_out, int out_size)
{
    const float* x       = (const float*)d_in[0];
    const float* v_first = (const float*)d_in[1];
    const float* x_r = (const float*)d_in[2];
    const float* x_w = (const float*)d_in[3];
    const float* x_k = (const float*)d_in[4];
    const float* x_v = (const float*)d_in[5];
    const float* x_a = (const float*)d_in[6];
    const float* x_g = (const float*)d_in[7];
    const float* w0  = (const float*)d_in[8];
    const float* w1  = (const float*)d_in[9];
    const float* w2  = (const float*)d_in[10];
    const float* a0  = (const float*)d_in[11];
    const float* a1  = (const float*)d_in[12];
    const float* a2  = (const float*)d_in[13];
    const float* v0  = (const float*)d_in[14];
    const float* v1  = (const float*)d_in[15];
    const float* v2  = (const float*)d_in[16];
    const float* g1  = (const float*)d_in[17];
    const float* g2  = (const float*)d_in[18];
    const float* k_k = (const float*)d_in[19];
    const float* k_a = (const float*)d_in[20];
    const float* r_k = (const float*)d_in[21];
    const float* gate_w = (const float*)d_in[22];
    const float* ln_g = (const float*)d_in[23];
    const float* ln_b = (const float*)d_in[24];
    const float* Wr = (const float*)d_in[25];
    const float* Wk = (const float*)d_in[26];
    const float* Wv = (const float*)d_in[27];
    const float* Wo = (const float*)d_in[28];
    float* out = (float*)d_out;

    if (!s_init) {
        cudaGetSymbolAddress((void**)&P_xr, g_xr);
        cudaGetSymbolAddress((void**)&P_xw, g_xw);
        cudaGetSymbolAddress((void**)&P_xk, g_xk);
        cudaGetSymbolAddress((void**)&P_xv, g_xv);
        cudaGetSymbolAddress((void**)&P_xa, g_xa);
        cudaGetSymbolAddress((void**)&P_xg, g_xg);
        cudaGetSymbolAddress((void**)&P_r, g_r);
        cudaGetSymbolAddress((void**)&P_k, g_k);
        cudaGetSymbolAddress((void**)&P_vraw, g_vraw);
        cudaGetSymbolAddress((void**)&P_hw, g_hw);
        cudaGetSymbolAddress((void**)&P_ha, g_ha);
        cudaGetSymbolAddress((void**)&P_hv, g_hv);
        cudaGetSymbolAddress((void**)&P_hg, g_hg);
        cudaGetSymbolAddress((void**)&P_dec, g_dec);
        cudaGetSymbolAddress((void**)&P_a, g_a);
        cudaGetSymbolAddress((void**)&P_v, g_v);
        cudaGetSymbolAddress((void**)&P_g, g_g);
        cudaGetSymbolAddress((void**)&P_z, g_z);
        s_init = true;
    }

    // 1) token shift + mixes + gate
    prep_kernel<<<BT, 128>>>(x, x_r, x_w, x_k, x_v, x_a, x_g, gate_w);

    // 2) big QKV GEMMs (A @ W^T), one launch
    {
        GemmJobs J = {};
        J.count = 3;
        J.tileStart[0] = 0; J.tileStart[1] = 8; J.tileStart[2] = 16; J.tileStart[3] = 24; J.tileStart[4] = 24;
        const float* As_[3] = { P_xr, P_xk, P_xv };
        const float* Bs_[3] = { Wr, Wk, Wv };
        float* Cs_[3] = { P_r, P_k, P_vraw };
        for (int jj = 0; jj < 3; jj++) {
            J.A[jj] = As_[jj]; J.Bm[jj] = Bs_[jj]; J.Cm[jj] = Cs_[jj];
            J.N[jj] = 512; J.K[jj] = 512; J.transb[jj] = 1; J.act[jj] = 0;
            J.bias[jj] = nullptr; J.aux1[jj] = nullptr; J.aux2[jj] = nullptr;
        }
        gemm_multi<<<dim3(24, 32), 256>>>(J);
    }

    // 3) stage-1 hidden GEMMs (A @ B), one launch
    {
        GemmJobs J = {};
        J.count = 4;
        J.tileStart[0] = 0; J.tileStart[1] = 1; J.tileStart[2] = 2; J.tileStart[3] = 3; J.tileStart[4] = 5;
        J.A[0] = P_xw; J.Bm[0] = w1; J.Cm[0] = P_hw; J.N[0] = 64;  J.K[0] = 512; J.transb[0] = 0; J.act[0] = 1;
        J.A[1] = P_xa; J.Bm[1] = a1; J.Cm[1] = P_ha; J.N[1] = 64;  J.K[1] = 512; J.transb[1] = 0; J.act[1] = 0;
        J.A[2] = x;    J.Bm[2] = v1; J.Cm[2] = P_hv; J.N[2] = 32;  J.K[2] = 512; J.transb[2] = 0; J.act[2] = 0;
        J.A[3] = P_xg; J.Bm[3] = g1; J.Cm[3] = P_hg; J.N[3] = 128; J.K[3] = 512; J.transb[3] = 0; J.act[3] = 2;
        for (int jj = 0; jj < 4; jj++) { J.bias[jj] = nullptr; J.aux1[jj] = nullptr; J.aux2[jj] = nullptr; }
        gemm_multi<<<dim3(5, 32), 256>>>(J);
    }

    // 4) stage-2 GEMMs with fused epilogues, one launch
    {
        GemmJobs J = {};
        J.count = 4;
        J.tileStart[0] = 0; J.tileStart[1] = 8; J.tileStart[2] = 16; J.tileStart[3] = 24; J.tileStart[4] = 32;
        J.A[0] = P_hw; J.Bm[0] = w2; J.Cm[0] = P_dec; J.N[0] = 512; J.K[0] = 64;  J.transb[0] = 0; J.act[0] = 3;
        J.bias[0] = w0; J.aux1[0] = nullptr; J.aux2[0] = nullptr;
        J.A[1] = P_ha; J.Bm[1] = a2; J.Cm[1] = P_a; J.N[1] = 512; J.K[1] = 64;  J.transb[1] = 0; J.act[1] = 2;
        J.bias[1] = a0; J.aux1[1] = nullptr; J.aux2[1] = nullptr;
        J.A[2] = P_hv; J.Bm[2] = v2; J.Cm[2] = P_v; J.N[2] = 512; J.K[2] = 32;  J.transb[2] = 0; J.act[2] = 4;
        J.bias[2] = v0; J.aux1[2] = P_vraw; J.aux2[2] = v_first;
        J.A[3] = P_hg; J.Bm[3] = g2; J.Cm[3] = P_g; J.N[3] = 512; J.K[3] = 128; J.transb[3] = 0; J.act[3] = 0;
        J.bias[3] = nullptr; J.aux1[3] = nullptr; J.aux2[3] = nullptr;
        gemm_multi<<<dim3(32, 32), 256>>>(J);
    }

    // 5) kk normalize, k', aa, bb
    post_kernel<<<BT, 128>>>(k_k, k_a);

    // 6) bidirectional WKV7 scan — 128 blocks, barrier-free
    scan_kernel<<<128, 128>>>();

    // 7) combine + groupnorm + residual + *g
    combine_kernel<<<BT, 128>>>(r_k, ln_g, ln_b);

    // 8) out = z @ Wo^T
    {
        GemmJobs J = {};
        J.count = 1;
        J.tileStart[0] = 0; J.tileStart[1] = 8; J.tileStart[2] = 8; J.tileStart[3] = 8; J.tileStart[4] = 8;
        J.A[0] = P_z; J.Bm[0] = Wo; J.Cm[0] = out;
        J.N[0] = 512; J.K[0] = 512; J.transb[0] = 1; J.act[0] = 0;
        J.bias[0] = nullptr; J.aux1[0] = nullptr; J.aux2[0] = nullptr;
        gemm_multi<<<dim3(8, 32), 256>>>(J);
    }

    // 9) v_first passthrough if the flattened output includes it
    if (out_size >= 2 * BTC) {
        cudaMemcpyAsync(out + BTC, v_first, (size_t)BTC * sizeof(float),
                        cudaMemcpyDeviceToDevice, 0);
    }
}

// round 3
// speedup vs baseline: 1.4724x; 1.2649x over previous
#include <cuda_runtime.h>
#include <cstdint>
#include <math.h>

// Problem sizes (fixed)
#define BB   4
#define TT   1024
#define CC   512
#define HH   8
#define NN   64
#define BT   (BB*TT)        // 4096
#define BTC  (BT*CC)        // 2097152

// ---------------------------------------------------------------------------
// Workspace (static __device__ arrays; no allocation at runtime)
// ---------------------------------------------------------------------------
__device__ float g_xr[BTC], g_xw[BTC], g_xk[BTC], g_xv[BTC], g_xa[BTC], g_xg[BTC];
__device__ float g_gate[BT*HH];
__device__ float g_r[BTC], g_k[BTC], g_vraw[BTC];
__device__ float g_hw[BT*64], g_ha[BT*64], g_hv[BT*32], g_hg[BT*128];
__device__ float g_dec[BTC], g_a[BTC], g_v[BTC], g_g[BTC];
__device__ float g_kp[BTC], g_aa[BTC], g_bb[BTC];
__device__ float g_yf[BTC], g_yb[BTC], g_z[BTC];

// ---------------------------------------------------------------------------
// Kernel 1: token shift, six mixes, per-head gate
// ---------------------------------------------------------------------------
__global__ void prep_kernel(const float* __restrict__ x,
                            const float* __restrict__ mr, const float* __restrict__ mw,
                            const float* __restrict__ mk, const float* __restrict__ mv,
                            const float* __restrict__ ma, const float* __restrict__ mg,
                            const float* __restrict__ gate_w)
{
    int bt = blockIdx.x;
    int t  = bt & (TT - 1);
    int tid = threadIdx.x;
    int c  = tid * 4;
    size_t base = (size_t)bt * CC + c;

    float4 xc = *(const float4*)(x + base);
    float4 xp = make_float4(0.f, 0.f, 0.f, 0.f);
    if (t != 0) xp = *(const float4*)(x + base - CC);

    float4 xx;
    xx.x = xp.x - xc.x; xx.y = xp.y - xc.y; xx.z = xp.z - xc.z; xx.w = xp.w - xc.w;

#define MIXOUT(dst, mvptr)                                                    \
    { float4 m = *(const float4*)(mvptr + c); float4 o;                       \
      o.x = xc.x + xx.x * m.x; o.y = xc.y + xx.y * m.y;                       \
      o.z = xc.z + xx.z * m.z; o.w = xc.w + xx.w * m.w;                       \
      *(float4*)(dst + base) = o; }
    MIXOUT(g_xr, mr); MIXOUT(g_xw, mw); MIXOUT(g_xk, mk);
    MIXOUT(g_xv, mv); MIXOUT(g_xa, ma); MIXOUT(g_xg, mg);
#undef MIXOUT

    float4 gw = *(const float4*)(gate_w + c);
    float p = xx.x*gw.x + xx.y*gw.y + xx.z*gw.z + xx.w*gw.w;
    #pragma unroll
    for (int o = 1; o < 16; o <<= 1) p += __shfl_xor_sync(0xffffffffu, p, o);
    if ((tid & 15) == 0)
        g_gate[bt*HH + (tid >> 4)] = 1.f / (1.f + expf(-p));
}

// ---------------------------------------------------------------------------
// Generic multi-job SGEMM with transposed smem tiles for vector LDS.
// ---------------------------------------------------------------------------
#define GBM 128
#define GBN 64
#define GBK 16

struct GemmJobs {
    int count;
    int tileStart[5];
    const float* A[4];
    const float* Bm[4];
    float*       Cm[4];
    int N[4];
    int K[4];
    int transb[4];
    int act[4];
    const float* bias[4];
    const float* aux1[4];
    const float* aux2[4];
};

__global__ __launch_bounds__(256, 2) void gemm_multi(GemmJobs J)
{
    __shared__ __align__(16) float As[GBK][GBM + 4];   // [k][m]
    __shared__ __align__(16) float Bs[GBK][GBN + 4];   // [k][n]

    int bx = blockIdx.x;
    int j = 0;
    while (bx >= J.tileStart[j + 1]) ++j;
    int n0 = (bx - J.tileStart[j]) * GBN;
    int m0 = blockIdx.y * GBM;

    const float* A = J.A[j];
    const float* B = J.Bm[j];
    float*       C = J.Cm[j];
    const int N = J.N[j];
    const int K = J.K[j];
    const int tb = J.transb[j];

    int tid = threadIdx.x;
    int tx = tid & 15, ty = tid >> 4;

    float acc[8][4];
    #pragma unroll
    for (int im = 0; im < 8; im++)
        #pragma unroll
        for (int in = 0; in < 4; in++) acc[im][in] = 0.f;

    for (int k0 = 0; k0 < K; k0 += GBK) {
        #pragma unroll
        for (int it = 0; it < 2; it++) {
            int lid = tid + it * 256;
            int row = lid >> 2, kc = lid & 3;
            float4 v = *(const float4*)(A + (size_t)(m0 + row) * K + k0 + kc * 4);
            As[kc*4+0][row] = v.x;
            As[kc*4+1][row] = v.y;
            As[kc*4+2][row] = v.z;
            As[kc*4+3][row] = v.w;
        }
        if (tb) {
            int row = tid >> 2, kc = tid & 3;
            float4 v = *(const float4*)(B + (size_t)(n0 + row) * K + k0 + kc * 4);
            Bs[kc*4+0][row] = v.x;
            Bs[kc*4+1][row] = v.y;
            Bs[kc*4+2][row] = v.z;
            Bs[kc*4+3][row] = v.w;
        } else {
            int kr = tid >> 4, c4 = (tid & 15) * 4;
            float4 v = make_float4(0.f, 0.f, 0.f, 0.f);
            if (n0 + c4 < N)
                v = *(const float4*)(B + (size_t)(k0 + kr) * N + n0 + c4);
            *(float4*)&Bs[kr][c4] = v;
        }
        __syncthreads();

        #pragma unroll
        for (int kk = 0; kk < GBK; kk++) {
            float4 bf = *(const float4*)&Bs[kk][tx * 4];
            float4 a0 = *(const float4*)&As[kk][ty * 8];
            float4 a1 = *(const float4*)&As[kk][ty * 8 + 4];
            float af[8] = {a0.x, a0.y, a0.z, a0.w, a1.x, a1.y, a1.z, a1.w};
            float bb2[4] = {bf.x, bf.y, bf.z, bf.w};
            #pragma unroll
            for (int im = 0; im < 8; im++)
                #pragma unroll
                for (int in = 0; in < 4; in++) acc[im][in] += af[im] * bb2[in];
        }
        __syncthreads();
    }

    const int act = J.act[j];
    const float* bias = J.bias[j];
    const float* aux1 = J.aux1[j];
    const float* aux2 = J.aux2[j];

    #pragma unroll
    for (int im = 0; im < 8; im++) {
        int row = m0 + ty * 8 + im;
        #pragma unroll
        for (int in = 0; in < 4; in++) {
            int col = n0 + tx * 4 + in;
            if (col < N) {
                size_t idx = (size_t)row * N + col;
                float v = acc[im][in];
                float o;
                if (act == 0) {
                    o = v;
                } else if (act == 1) {
                    o = tanhf(v);
                } else if (act == 2) {
                    float z = v + (bias ? bias[col] : 0.f);
                    o = 1.f / (1.f + expf(-z));
                } else if (act == 3) {
                    float z = v + bias[col];
                    float s = 1.f / (1.f + expf(-z));
                    o = expf(-0.60653065971263342f * s);
                } else {
                    float z = v + bias[col];
                    float s = 1.f / (1.f + expf(-z));
                    float vr = aux1[idx];
                    o = vr + (aux2[idx] - vr) * s;
                }
                C[idx] = o;
            }
        }
    }
}

// ---------------------------------------------------------------------------
// Kernel: post — kk normalization per head, k' update, aa=-kk, bb=kk*a
// ---------------------------------------------------------------------------
__global__ void post_kernel(const float* __restrict__ k_k, const float* __restrict__ k_a)
{
    int bt = blockIdx.x;
    int tid = threadIdx.x;
    int c = tid * 4;
    size_t base = (size_t)bt * CC + c;

    float4 kv = *(const float4*)(g_k + base);
    float4 av = *(const float4*)(g_a + base);
    float4 kkc = *(const float4*)(k_k + c);
    float4 kac = *(const float4*)(k_a + c);

    float4 kk;
    kk.x = kv.x * kkc.x; kk.y = kv.y * kkc.y; kk.z = kv.z * kkc.z; kk.w = kv.w * kkc.w;
    float ss = kk.x*kk.x + kk.y*kk.y + kk.z*kk.z + kk.w*kk.w;
    #pragma unroll
    for (int o = 1; o < 16; o <<= 1) ss += __shfl_xor_sync(0xffffffffu, ss, o);

    float nrm = sqrtf(ss);
    float inv = 1.f / fmaxf(nrm, 1e-12f);

    float4 aa, bb, kp;
    aa.x = -kk.x * inv; aa.y = -kk.y * inv; aa.z = -kk.z * inv; aa.w = -kk.w * inv;
    bb.x = kk.x * inv * av.x; bb.y = kk.y * inv * av.y;
    bb.z = kk.z * inv * av.z; bb.w = kk.w * inv * av.w;
    kp.x = kv.x * (1.f + (av.x - 1.f) * kac.x);
    kp.y = kv.y * (1.f + (av.y - 1.f) * kac.y);
    kp.z = kv.z * (1.f + (av.z - 1.f) * kac.z);
    kp.w = kv.w * (1.f + (av.w - 1.f) * kac.w);

    *(float4*)(g_aa + base) = aa;
    *(float4*)(g_bb + base) = bb;
    *(float4*)(g_kp + base) = kp;
}

// ---------------------------------------------------------------------------
// Kernel: bidirectional WKV7 scan — fused y/sa' partials, depth-2 prefetch.
// grid = 128 blocks (dir*64 + b*16 + h*2 + rowgroup), 128 threads.
// thread (i = rg*32 + tid>>2, q = tid&3) owns row i, cols [q*16, q*16+16).
//
// Per step t (with sa_t already reduced):
//   S <- S*d_t + sa_t*b_t + v_t*k_t
//   y_t   = S . r_t        (partial, 4 chains)
//   sa'_  = S . a_{t+1}    (partial, 4 chains)  <- A prefetched one step ahead
//   issue prefetch for t+2 (R/D/K/B/V) and t+3 (A)
//   reduce y_t and sa' together (shfl latencies overlap)
// ---------------------------------------------------------------------------
template<int CS, int NS>
__device__ __forceinline__ void scan_step(
    int T, float (&S)[16],
    float (&RB)[2][16], float (&DB)[2][16], float (&KB)[2][16],
    float (&BF)[2][16], float (&AB)[2][16], float (&VB)[2],
    float& sa,
    const float*& pr2, const float*& pd2, const float*& pk2,
    const float*& pb2, const float*& pv2, const float*& pa3,
    float*& py, int stride, int q)
{
    float y0 = 0.f, y1 = 0.f, y2 = 0.f, y3 = 0.f;
    float z0 = 0.f, z1 = 0.f, z2 = 0.f, z3 = 0.f;
    float Vv = VB[CS];
    #pragma unroll
    for (int j = 0; j < 4; j++) {
        float sj;
        sj = S[j]     * DB[CS][j]      + sa * BF[CS][j]      + Vv * KB[CS][j];
        S[j] = sj;      y0 += sj * RB[CS][j];      z0 += sj * AB[NS][j];
        sj = S[4+j]   * DB[CS][4+j]    + sa * BF[CS][4+j]    + Vv * KB[CS][4+j];
        S[4+j] = sj;    y1 += sj * RB[CS][4+j];    z1 += sj * AB[NS][4+j];
        sj = S[8+j]   * DB[CS][8+j]    + sa * BF[CS][8+j]    + Vv * KB[CS][8+j];
        S[8+j] = sj;    y2 += sj * RB[CS][8+j];    z2 += sj * AB[NS][8+j];
        sj = S[12+j]  * DB[CS][12+j]   + sa * BF[CS][12+j]   + Vv * KB[CS][12+j];
        S[12+j] = sj;   y3 += sj * RB[CS][12+j];   z3 += sj * AB[NS][12+j];
    }
    float y   = (y0 + y1) + (y2 + y3);
    float sap = (z0 + z1) + (z2 + z3);

    // prefetch step T+2 into slot CS (just consumed)
    if (T + 2 < TT) {
        #pragma unroll
        for (int u = 0; u < 4; u++) {
            *(float4*)&RB[CS][u*4] = *(const float4*)(pr2 + u*4);
            *(float4*)&DB[CS][u*4] = *(const float4*)(pd2 + u*4);
            *(float4*)&KB[CS][u*4] = *(const float4*)(pk2 + u*4);
            *(float4*)&BF[CS][u*4] = *(const float4*)(pb2 + u*4);
        }
        VB[CS] = *pv2;
    }
    pr2 += stride; pd2 += stride; pk2 += stride; pb2 += stride; pv2 += stride;
    // prefetch A for step T+3 into slot NS (A[T+1] just consumed)
    if (T + 3 < TT) {
        #pragma unroll
        for (int u = 0; u < 4; u++)
            *(float4*)&AB[NS][u*4] = *(const float4*)(pa3 + u*4);
    }
    pa3 += stride;

    // overlapped reductions
    y   += __shfl_xor_sync(0xffffffffu, y, 1);
    sap += __shfl_xor_sync(0xffffffffu, sap, 1);
    y   += __shfl_xor_sync(0xffffffffu, y, 2);
    sap += __shfl_xor_sync(0xffffffffu, sap, 2);

    if (q == 0) *py = y;
    py += stride;
    sa = sap;
}

__global__ __launch_bounds__(128, 1) void scan_kernel()
{
    int bx = blockIdx.x;
    int dir = bx >> 6;
    int b   = (bx >> 4) & 3;
    int h   = (bx >> 1) & 7;
    int rg  = bx & 1;
    int tid = threadIdx.x;
    int i   = rg * 32 + (tid >> 2);
    int q   = tid & 3;
    int c0  = q * 16;

    int t0 = dir ? (TT - 1) : 0;
    int stride = dir ? -CC : CC;
    size_t off = (size_t)(b * TT + t0) * CC + h * NN;

    const float* pr = g_r   + off + c0;
    const float* pd = g_dec + off + c0;
    const float* pk = g_kp  + off + c0;
    const float* pa = g_aa  + off + c0;
    const float* pb = g_bb  + off + c0;
    const float* pv = g_v   + off + i;
    float* py = (dir ? g_yb : g_yf) + off + i;

    float S[16];
    #pragma unroll
    for (int j = 0; j < 16; j++) S[j] = 0.f;

    float RB[2][16], DB[2][16], KB[2][16], BF[2][16], AB[2][16], VB[2];

    // prologue: t=0 -> slot0, t=1 -> slot1 for R/D/K/B/V; A[1]->slot1, A[2]->slot0
    #pragma unroll
    for (int u = 0; u < 4; u++) {
        *(float4*)&RB[0][u*4] = *(const float4*)(pr + u*4);
        *(float4*)&DB[0][u*4] = *(const float4*)(pd + u*4);
        *(float4*)&KB[0][u*4] = *(const float4*)(pk + u*4);
        *(float4*)&BF[0][u*4] = *(const float4*)(pb + u*4);
        *(float4*)&RB[1][u*4] = *(const float4*)(pr + stride + u*4);
        *(float4*)&DB[1][u*4] = *(const float4*)(pd + stride + u*4);
        *(float4*)&KB[1][u*4] = *(const float4*)(pk + stride + u*4);
        *(float4*)&BF[1][u*4] = *(const float4*)(pb + stride + u*4);
        *(float4*)&AB[1][u*4] = *(const float4*)(pa + stride + u*4);
        *(float4*)&AB[0][u*4] = *(const float4*)(pa + 2*stride + u*4);
    }
    VB[0] = *pv;
    VB[1] = *(pv + stride);

    const float* pr2 = pr + 2*stride;
    const float* pd2 = pd + 2*stride;
    const float* pk2 = pk + 2*stride;
    const float* pb2 = pb + 2*stride;
    const float* pv2 = pv + 2*stride;
    const float* pa3 = pa + 3*stride;

    float sa = 0.f;

    for (int t = 0; t < TT; t += 2) {
        scan_step<0,1>(t,   S, RB, DB, KB, BF, AB, VB, sa,
                       pr2, pd2, pk2, pb2, pv2, pa3, py, stride, q);
        scan_step<1,0>(t+1, S, RB, DB, KB, BF, AB, VB, sa,
                       pr2, pd2, pk2, pb2, pv2, pa3, py, stride, q);
    }
}

// ---------------------------------------------------------------------------
// Kernel: combine — gate-mix fwd/bwd, groupnorm, residual, * g
// ---------------------------------------------------------------------------
__global__ void combine_kernel(const float* __restrict__ r_k,
                               const float* __restrict__ ln_g,
                               const float* __restrict__ ln_b)
{
    int bt = blockIdx.x;
    int tid = threadIdx.x;
    int c = tid * 4;
    int h = tid >> 4;
    size_t base = (size_t)bt * CC + c;

    float4 yf = *(const float4*)(g_yf + base);
    float4 yb = *(const float4*)(g_yb + base);
    float gate = g_gate[bt * HH + h];

    float4 xo;
    xo.x = gate * yf.x + (1.f - gate) * yb.x;
    xo.y = gate * yf.y + (1.f - gate) * yb.y;
    xo.z = gate * yf.z + (1.f - gate) * yb.z;
    xo.w = gate * yf.w + (1.f - gate) * yb.w;

    float4 rv = *(const float4*)(g_r + base);
    float4 kp = *(const float4*)(g_kp + base);
    float4 vv = *(const float4*)(g_v + base);
    float4 gv = *(const float4*)(g_g + base);
    float4 rk = *(const float4*)(r_k + c);

    float sum = xo.x + xo.y + xo.z + xo.w;
    float sq  = xo.x*xo.x + xo.y*xo.y + xo.z*xo.z + xo.w*xo.w;
    float sres = rv.x*kp.x*rk.x + rv.y*kp.y*rk.y + rv.z*kp.z*rk.z + rv.w*kp.w*rk.w;
    #pragma unroll
    for (int o = 1; o < 16; o <<= 1) {
        sum  += __shfl_xor_sync(0xffffffffu, sum, o);
        sq   += __shfl_xor_sync(0xffffffffu, sq, o);
        sres += __shfl_xor_sync(0xffffffffu, sres, o);
    }
    float mu = sum * (1.f / 64.f);
    float var = sq * (1.f / 64.f) - mu * mu;
    float rstd = rsqrtf(var + 0.00064f);

    float4 lg = *(const float4*)(ln_g + c);
    float4 lb = *(const float4*)(ln_b + c);

    float4 z;
    z.x = ((xo.x - mu) * rstd * lg.x + lb.x + sres * vv.x) * gv.x;
    z.y = ((xo.y - mu) * rstd * lg.y + lb.y + sres * vv.y) * gv.y;
    z.z = ((xo.z - mu) * rstd * lg.z + lb.z + sres * vv.z) * gv.z;
    z.w = ((xo.w - mu) * rstd * lg.w + lb.w + sres * vv.w) * gv.w;
    *(float4*)(g_z + base) = z;
}

// ---------------------------------------------------------------------------
// Host launcher
// ---------------------------------------------------------------------------
static float *P_xr, *P_xw, *P_xk, *P_xv, *P_xa, *P_xg;
static float *P_r, *P_k, *P_vraw;
static float *P_hw, *P_ha, *P_hv, *P_hg;
static float *P_dec, *P_a, *P_v, *P_g;
static float *P_z;
static bool s_init = false;

extern "C" void kernel_launch(void* const* d_in, const int* in_sizes, int n_in,
                              void* d_out, int out_size)
{
    const float* x       = (const float*)d_in[0];
    const float* v_first = (const float*)d_in[1];
    const float* x_r = (const float*)d_in[2];
    const float* x_w = (const float*)d_in[3];
    const float* x_k = (const float*)d_in[4];
    const float* x_v = (const float*)d_in[5];
    const float* x_a = (const float*)d_in[6];
    const float* x_g = (const float*)d_in[7];
    const float* w0  = (const float*)d_in[8];
    const float* w1  = (const float*)d_in[9];
    const float* w2  = (const float*)d_in[10];
    const float* a0  = (const float*)d_in[11];
    const float* a1  = (const float*)d_in[12];
    const float* a2  = (const float*)d_in[13];
    const float* v0  = (const float*)d_in[14];
    const float* v1  = (const float*)d_in[15];
    const float* v2  = (const float*)d_in[16];
    const float* g1  = (const float*)d_in[17];
    const float* g2  = (const float*)d_in[18];
    const float* k_k = (const float*)d_in[19];
    const float* k_a = (const float*)d_in[20];
    const float* r_k = (const float*)d_in[21];
    const float* gate_w = (const float*)d_in[22];
    const float* ln_g = (const float*)d_in[23];
    const float* ln_b = (const float*)d_in[24];
    const float* Wr = (const float*)d_in[25];
    const float* Wk = (const float*)d_in[26];
    const float* Wv = (const float*)d_in[27];
    const float* Wo = (const float*)d_in[28];
    float* out = (float*)d_out;

    if (!s_init) {
        cudaGetSymbolAddress((void**)&P_xr, g_xr);
        cudaGetSymbolAddress((void**)&P_xw, g_xw);
        cudaGetSymbolAddress((void**)&P_xk, g_xk);
        cudaGetSymbolAddress((void**)&P_xv, g_xv);
        cudaGetSymbolAddress((void**)&P_xa, g_xa);
        cudaGetSymbolAddress((void**)&P_xg, g_xg);
        cudaGetSymbolAddress((void**)&P_r, g_r);
        cudaGetSymbolAddress((void**)&P_k, g_k);
        cudaGetSymbolAddress((void**)&P_vraw, g_vraw);
        cudaGetSymbolAddress((void**)&P_hw, g_hw);
        cudaGetSymbolAddress((void**)&P_ha, g_ha);
        cudaGetSymbolAddress((void**)&P_hv, g_hv);
        cudaGetSymbolAddress((void**)&P_hg, g_hg);
        cudaGetSymbolAddress((void**)&P_dec, g_dec);
        cudaGetSymbolAddress((void**)&P_a, g_a);
        cudaGetSymbolAddress((void**)&P_v, g_v);
        cudaGetSymbolAddress((void**)&P_g, g_g);
        cudaGetSymbolAddress((void**)&P_z, g_z);
        s_init = true;
    }

    // 1) token shift + mixes + gate
    prep_kernel<<<BT, 128>>>(x, x_r, x_w, x_k, x_v, x_a, x_g, gate_w);

    // 2) big QKV GEMMs (A @ W^T), one launch
    {
        GemmJobs J = {};
        J.count = 3;
        J.tileStart[0] = 0; J.tileStart[1] = 8; J.tileStart[2] = 16; J.tileStart[3] = 24; J.tileStart[4] = 24;
        const float* As_[3] = { P_xr, P_xk, P_xv };
        const float* Bs_[3] = { Wr, Wk, Wv };
        float* Cs_[3] = { P_r, P_k, P_vraw };
        for (int jj = 0; jj < 3; jj++) {
            J.A[jj] = As_[jj]; J.Bm[jj] = Bs_[jj]; J.Cm[jj] = Cs_[jj];
            J.N[jj] = 512; J.K[jj] = 512; J.transb[jj] = 1; J.act[jj] = 0;
            J.bias[jj] = nullptr; J.aux1[jj] = nullptr; J.aux2[jj] = nullptr;
        }
        gemm_multi<<<dim3(24, 32), 256>>>(J);
    }

    // 3) stage-1 hidden GEMMs (A @ B), one launch
    {
        GemmJobs J = {};
        J.count = 4;
        J.tileStart[0] = 0; J.tileStart[1] = 1; J.tileStart[2] = 2; J.tileStart[3] = 3; J.tileStart[4] = 5;
        J.A[0] = P_xw; J.Bm[0] = w1; J.Cm[0] = P_hw; J.N[0] = 64;  J.K[0] = 512; J.transb[0] = 0; J.act[0] = 1;
        J.A[1] = P_xa; J.Bm[1] = a1; J.Cm[1] = P_ha; J.N[1] = 64;  J.K[1] = 512; J.transb[1] = 0; J.act[1] = 0;
        J.A[2] = x;    J.Bm[2] = v1; J.Cm[2] = P_hv; J.N[2] = 32;  J.K[2] = 512; J.transb[2] = 0; J.act[2] = 0;
        J.A[3] = P_xg; J.Bm[3] = g1; J.Cm[3] = P_hg; J.N[3] = 128; J.K[3] = 512; J.transb[3] = 0; J.act[3] = 2;
        for (int jj = 0; jj < 4; jj++) { J.bias[jj] = nullptr; J.aux1[jj] = nullptr; J.aux2[jj] = nullptr; }
        gemm_multi<<<dim3(5, 32), 256>>>(J);
    }

    // 4) stage-2 GEMMs with fused epilogues, one launch
    {
        GemmJobs J = {};
        J.count = 4;
        J.tileStart[0] = 0; J.tileStart[1] = 8; J.tileStart[2] = 16; J.tileStart[3] = 24; J.tileStart[4] = 32;
        J.A[0] = P_hw; J.Bm[0] = w2; J.Cm[0] = P_dec; J.N[0] = 512; J.K[0] = 64;  J.transb[0] = 0; J.act[0] = 3;
        J.bias[0] = w0; J.aux1[0] = nullptr; J.aux2[0] = nullptr;
        J.A[1] = P_ha; J.Bm[1] = a2; J.Cm[1] = P_a; J.N[1] = 512; J.K[1] = 64;  J.transb[1] = 0; J.act[1] = 2;
        J.bias[1] = a0; J.aux1[1] = nullptr; J.aux2[1] = nullptr;
        J.A[2] = P_hv; J.Bm[2] = v2; J.Cm[2] = P_v; J.N[2] = 512; J.K[2] = 32;  J.transb[2] = 0; J.act[2] = 4;
        J.bias[2] = v0; J.aux1[2] = P_vraw; J.aux2[2] = v_first;
        J.A[3] = P_hg; J.Bm[3] = g2; J.Cm[3] = P_g; J.N[3] = 512; J.K[3] = 128; J.transb[3] = 0; J.act[3] = 0;
        J.bias[3] = nullptr; J.aux1[3] = nullptr; J.aux2[3] = nullptr;
        gemm_multi<<<dim3(32, 32), 256>>>(J);
    }

    // 5) kk normalize, k', aa, bb
    post_kernel<<<BT, 128>>>(k_k, k_a);

    // 6) bidirectional WKV7 scan — 128 blocks, barrier-free, fused partials
    scan_kernel<<<128, 128>>>();

    // 7) combine + groupnorm + residual + *g
    combine_kernel<<<BT, 128>>>(r_k, ln_g, ln_b);

    // 8) out = z @ Wo^T
    {
        GemmJobs J = {};
        J.count = 1;
        J.tileStart[0] = 0; J.tileStart[1] = 8; J.tileStart[2] = 8; J.tileStart[3] = 8; J.tileStart[4] = 8;
        J.A[0] = P_z; J.Bm[0] = Wo; J.Cm[0] = out;
        J.N[0] = 512; J.K[0] = 512; J.transb[0] = 1; J.act[0] = 0;
        J.bias[0] = nullptr; J.aux1[0] = nullptr; J.aux2[0] = nullptr;
        gemm_multi<<<dim3(8, 32), 256>>>(J);
    }

    // 9) v_first passthrough if the flattened output includes it
    if (out_size >= 2 * BTC) {
        cudaMemcpyAsync(out + BTC, v_first, (size_t)BTC * sizeof(float),
                        cudaMemcpyDeviceToDevice, 0);
    }
}

// round 4
// speedup vs baseline: 1.5149x; 1.0289x over previous
#include <cuda_runtime.h>
#include <cstdint>
#include <math.h>

// Problem sizes (fixed)
#define BB   4
#define TT   1024
#define CC   512
#define HH   8
#define NN   64
#define BT   (BB*TT)        // 4096
#define BTC  (BT*CC)        // 2097152

// ---------------------------------------------------------------------------
// Workspace (static __device__ arrays; no allocation at runtime)
// ---------------------------------------------------------------------------
__device__ float g_xr[BTC], g_xw[BTC], g_xk[BTC], g_xv[BTC], g_xa[BTC], g_xg[BTC];
__device__ float g_gate[BT*HH];
__device__ float g_r[BTC], g_k[BTC], g_vraw[BTC];
__device__ float g_hw[BT*64], g_ha[BT*64], g_hv[BT*32], g_hg[BT*128];
__device__ float g_dec[BTC], g_a[BTC], g_v[BTC], g_g[BTC];
__device__ float g_kp[BTC], g_aa[BTC], g_bb[BTC];
__device__ float g_yf[BTC], g_yb[BTC], g_z[BTC];

// ---------------------------------------------------------------------------
// Kernel 1: token shift, six mixes, per-head gate
// ---------------------------------------------------------------------------
__global__ void prep_kernel(const float* __restrict__ x,
                            const float* __restrict__ mr, const float* __restrict__ mw,
                            const float* __restrict__ mk, const float* __restrict__ mv,
                            const float* __restrict__ ma, const float* __restrict__ mg,
                            const float* __restrict__ gate_w)
{
    int bt = blockIdx.x;
    int t  = bt & (TT - 1);
    int tid = threadIdx.x;
    int c  = tid * 4;
    size_t base = (size_t)bt * CC + c;

    float4 xc = *(const float4*)(x + base);
    float4 xp = make_float4(0.f, 0.f, 0.f, 0.f);
    if (t != 0) xp = *(const float4*)(x + base - CC);

    float4 xx;
    xx.x = xp.x - xc.x; xx.y = xp.y - xc.y; xx.z = xp.z - xc.z; xx.w = xp.w - xc.w;

#define MIXOUT(dst, mvptr)                                                    \
    { float4 m = *(const float4*)(mvptr + c); float4 o;                       \
      o.x = xc.x + xx.x * m.x; o.y = xc.y + xx.y * m.y;                       \
      o.z = xc.z + xx.z * m.z; o.w = xc.w + xx.w * m.w;                       \
      *(float4*)(dst + base) = o; }
    MIXOUT(g_xr, mr); MIXOUT(g_xw, mw); MIXOUT(g_xk, mk);
    MIXOUT(g_xv, mv); MIXOUT(g_xa, ma); MIXOUT(g_xg, mg);
#undef MIXOUT

    float4 gw = *(const float4*)(gate_w + c);
    float p = xx.x*gw.x + xx.y*gw.y + xx.z*gw.z + xx.w*gw.w;
    #pragma unroll
    for (int o = 1; o < 16; o <<= 1) p += __shfl_xor_sync(0xffffffffu, p, o);
    if ((tid & 15) == 0)
        g_gate[bt*HH + (tid >> 4)] = 1.f / (1.f + expf(-p));
}

// ---------------------------------------------------------------------------
// Generic multi-job SGEMM with transposed smem tiles for vector LDS.
// ---------------------------------------------------------------------------
#define GBM 128
#define GBN 64
#define GBK 16

struct GemmJobs {
    int count;
    int tileStart[5];
    const float* A[4];
    const float* Bm[4];
    float*       Cm[4];
    int N[4];
    int K[4];
    int transb[4];
    int act[4];
    const float* bias[4];
    const float* aux1[4];
    const float* aux2[4];
};

__global__ __launch_bounds__(256, 2) void gemm_multi(GemmJobs J)
{
    __shared__ __align__(16) float As[GBK][GBM + 4];   // [k][m]
    __shared__ __align__(16) float Bs[GBK][GBN + 4];   // [k][n]

    int bx = blockIdx.x;
    int j = 0;
    while (bx >= J.tileStart[j + 1]) ++j;
    int n0 = (bx - J.tileStart[j]) * GBN;
    int m0 = blockIdx.y * GBM;

    const float* A = J.A[j];
    const float* B = J.Bm[j];
    float*       C = J.Cm[j];
    const int N = J.N[j];
    const int K = J.K[j];
    const int tb = J.transb[j];

    int tid = threadIdx.x;
    int tx = tid & 15, ty = tid >> 4;

    float acc[8][4];
    #pragma unroll
    for (int im = 0; im < 8; im++)
        #pragma unroll
        for (int in = 0; in < 4; in++) acc[im][in] = 0.f;

    for (int k0 = 0; k0 < K; k0 += GBK) {
        #pragma unroll
        for (int it = 0; it < 2; it++) {
            int lid = tid + it * 256;
            int row = lid >> 2, kc = lid & 3;
            float4 v = *(const float4*)(A + (size_t)(m0 + row) * K + k0 + kc * 4);
            As[kc*4+0][row] = v.x;
            As[kc*4+1][row] = v.y;
            As[kc*4+2][row] = v.z;
            As[kc*4+3][row] = v.w;
        }
        if (tb) {
            int row = tid >> 2, kc = tid & 3;
            float4 v = *(const float4*)(B + (size_t)(n0 + row) * K + k0 + kc * 4);
            Bs[kc*4+0][row] = v.x;
            Bs[kc*4+1][row] = v.y;
            Bs[kc*4+2][row] = v.z;
            Bs[kc*4+3][row] = v.w;
        } else {
            int kr = tid >> 4, c4 = (tid & 15) * 4;
            float4 v = make_float4(0.f, 0.f, 0.f, 0.f);
            if (n0 + c4 < N)
                v = *(const float4*)(B + (size_t)(k0 + kr) * N + n0 + c4);
            *(float4*)&Bs[kr][c4] = v;
        }
        __syncthreads();

        #pragma unroll
        for (int kk = 0; kk < GBK; kk++) {
            float4 bf = *(const float4*)&Bs[kk][tx * 4];
            float4 a0 = *(const float4*)&As[kk][ty * 8];
            float4 a1 = *(const float4*)&As[kk][ty * 8 + 4];
            float af[8] = {a0.x, a0.y, a0.z, a0.w, a1.x, a1.y, a1.z, a1.w};
            float bb2[4] = {bf.x, bf.y, bf.z, bf.w};
            #pragma unroll
            for (int im = 0; im < 8; im++)
                #pragma unroll
                for (int in = 0; in < 4; in++) acc[im][in] += af[im] * bb2[in];
        }
        __syncthreads();
    }

    const int act = J.act[j];
    const float* bias = J.bias[j];
    const float* aux1 = J.aux1[j];
    const float* aux2 = J.aux2[j];

    #pragma unroll
    for (int im = 0; im < 8; im++) {
        int row = m0 + ty * 8 + im;
        #pragma unroll
        for (int in = 0; in < 4; in++) {
            int col = n0 + tx * 4 + in;
            if (col < N) {
                size_t idx = (size_t)row * N + col;
                float v = acc[im][in];
                float o;
                if (act == 0) {
                    o = v;
                } else if (act == 1) {
                    o = tanhf(v);
                } else if (act == 2) {
                    float z = v + (bias ? bias[col] : 0.f);
                    o = 1.f / (1.f + expf(-z));
                } else if (act == 3) {
                    float z = v + bias[col];
                    float s = 1.f / (1.f + expf(-z));
                    o = expf(-0.60653065971263342f * s);
                } else {
                    float z = v + bias[col];
                    float s = 1.f / (1.f + expf(-z));
                    float vr = aux1[idx];
                    o = vr + (aux2[idx] - vr) * s;
                }
                C[idx] = o;
            }
        }
    }
}

// ---------------------------------------------------------------------------
// Kernel: post — kk normalization per head, k' update, aa=-kk, bb=kk*a
// ---------------------------------------------------------------------------
__global__ void post_kernel(const float* __restrict__ k_k, const float* __restrict__ k_a)
{
    int bt = blockIdx.x;
    int tid = threadIdx.x;
    int c = tid * 4;
    size_t base = (size_t)bt * CC + c;

    float4 kv = *(const float4*)(g_k + base);
    float4 av = *(const float4*)(g_a + base);
    float4 kkc = *(const float4*)(k_k + c);
    float4 kac = *(const float4*)(k_a + c);

    float4 kk;
    kk.x = kv.x * kkc.x; kk.y = kv.y * kkc.y; kk.z = kv.z * kkc.z; kk.w = kv.w * kkc.w;
    float ss = kk.x*kk.x + kk.y*kk.y + kk.z*kk.z + kk.w*kk.w;
    #pragma unroll
    for (int o = 1; o < 16; o <<= 1) ss += __shfl_xor_sync(0xffffffffu, ss, o);

    float nrm = sqrtf(ss);
    float inv = 1.f / fmaxf(nrm, 1e-12f);

    float4 aa, bb, kp;
    aa.x = -kk.x * inv; aa.y = -kk.y * inv; aa.z = -kk.z * inv; aa.w = -kk.w * inv;
    bb.x = kk.x * inv * av.x; bb.y = kk.y * inv * av.y;
    bb.z = kk.z * inv * av.z; bb.w = kk.w * inv * av.w;
    kp.x = kv.x * (1.f + (av.x - 1.f) * kac.x);
    kp.y = kv.y * (1.f + (av.y - 1.f) * kac.y);
    kp.z = kv.z * (1.f + (av.z - 1.f) * kac.z);
    kp.w = kv.w * (1.f + (av.w - 1.f) * kac.w);

    *(float4*)(g_aa + base) = aa;
    *(float4*)(g_bb + base) = bb;
    *(float4*)(g_kp + base) = kp;
}

// ---------------------------------------------------------------------------
// Kernel: bidirectional WKV7 scan — 8 cols/thread, 256 thr/block, no spills.
// grid = 128 blocks (dir*64 + b*16 + h*2 + rowgroup), 256 threads.
// thread (i = rg*32 + tid>>3, q = tid&7) owns row i, cols [q*8, q*8+8).
// Fused y/sa' partials; depth-2 register double-buffer prefetch.
// ---------------------------------------------------------------------------
template<int CS, int NS>
__device__ __forceinline__ void scan_step(
    int T, float (&S)[8],
    float (&RB)[2][8], float (&DB)[2][8], float (&KB)[2][8],
    float (&BF)[2][8], float (&AB)[2][8], float (&VB)[2],
    float& sa,
    const float*& pr2, const float*& pd2, const float*& pk2,
    const float*& pb2, const float*& pv2, const float*& pa3,
    float*& py, int stride, int q)
{
    float y0 = 0.f, y1 = 0.f;
    float z0 = 0.f, z1 = 0.f;
    float Vv = VB[CS];
    #pragma unroll
    for (int j = 0; j < 4; j++) {
        float sj;
        sj = S[j]   * DB[CS][j]   + sa * BF[CS][j]   + Vv * KB[CS][j];
        S[j] = sj;    y0 += sj * RB[CS][j];    z0 += sj * AB[NS][j];
        sj = S[4+j] * DB[CS][4+j] + sa * BF[CS][4+j] + Vv * KB[CS][4+j];
        S[4+j] = sj;  y1 += sj * RB[CS][4+j];  z1 += sj * AB[NS][4+j];
    }
    float y   = y0 + y1;
    float sap = z0 + z1;

    // prefetch step T+2 into slot CS (just consumed)
    if (T + 2 < TT) {
        #pragma unroll
        for (int u = 0; u < 2; u++) {
            *(float4*)&RB[CS][u*4] = *(const float4*)(pr2 + u*4);
            *(float4*)&DB[CS][u*4] = *(const float4*)(pd2 + u*4);
            *(float4*)&KB[CS][u*4] = *(const float4*)(pk2 + u*4);
            *(float4*)&BF[CS][u*4] = *(const float4*)(pb2 + u*4);
        }
        VB[CS] = *pv2;
    }
    pr2 += stride; pd2 += stride; pk2 += stride; pb2 += stride; pv2 += stride;
    // prefetch A for step T+3 into slot NS (A[T+1] just consumed)
    if (T + 3 < TT) {
        #pragma unroll
        for (int u = 0; u < 2; u++)
            *(float4*)&AB[NS][u*4] = *(const float4*)(pa3 + u*4);
    }
    pa3 += stride;

    // overlapped 8-lane reductions (3 rounds each)
    y   += __shfl_xor_sync(0xffffffffu, y, 1);
    sap += __shfl_xor_sync(0xffffffffu, sap, 1);
    y   += __shfl_xor_sync(0xffffffffu, y, 2);
    sap += __shfl_xor_sync(0xffffffffu, sap, 2);
    y   += __shfl_xor_sync(0xffffffffu, y, 4);
    sap += __shfl_xor_sync(0xffffffffu, sap, 4);

    if (q == 0) *py = y;
    py += stride;
    sa = sap;
}

__global__ __launch_bounds__(256, 1) void scan_kernel()
{
    int bx = blockIdx.x;
    int dir = bx >> 6;
    int b   = (bx >> 4) & 3;
    int h   = (bx >> 1) & 7;
    int rg  = bx & 1;
    int tid = threadIdx.x;
    int i   = rg * 32 + (tid >> 3);
    int q   = tid & 7;
    int c0  = q * 8;

    int t0 = dir ? (TT - 1) : 0;
    int stride = dir ? -CC : CC;
    size_t off = (size_t)(b * TT + t0) * CC + h * NN;

    const float* pr = g_r   + off + c0;
    const float* pd = g_dec + off + c0;
    const float* pk = g_kp  + off + c0;
    const float* pa = g_aa  + off + c0;
    const float* pb = g_bb  + off + c0;
    const float* pv = g_v   + off + i;
    float* py = (dir ? g_yb : g_yf) + off + i;

    float S[8];
    #pragma unroll
    for (int j = 0; j < 8; j++) S[j] = 0.f;

    float RB[2][8], DB[2][8], KB[2][8], BF[2][8], AB[2][8], VB[2];

    // prologue: t=0 -> slot0, t=1 -> slot1 for R/D/K/B/V; A[1]->slot1, A[2]->slot0
    #pragma unroll
    for (int u = 0; u < 2; u++) {
        *(float4*)&RB[0][u*4] = *(const float4*)(pr + u*4);
        *(float4*)&DB[0][u*4] = *(const float4*)(pd + u*4);
        *(float4*)&KB[0][u*4] = *(const float4*)(pk + u*4);
        *(float4*)&BF[0][u*4] = *(const float4*)(pb + u*4);
        *(float4*)&RB[1][u*4] = *(const float4*)(pr + stride + u*4);
        *(float4*)&DB[1][u*4] = *(const float4*)(pd + stride + u*4);
        *(float4*)&KB[1][u*4] = *(const float4*)(pk + stride + u*4);
        *(float4*)&BF[1][u*4] = *(const float4*)(pb + stride + u*4);
        *(float4*)&AB[1][u*4] = *(const float4*)(pa + stride + u*4);
        *(float4*)&AB[0][u*4] = *(const float4*)(pa + 2*stride + u*4);
    }
    VB[0] = *pv;
    VB[1] = *(pv + stride);

    const float* pr2 = pr + 2*stride;
    const float* pd2 = pd + 2*stride;
    const float* pk2 = pk + 2*stride;
    const float* pb2 = pb + 2*stride;
    const float* pv2 = pv + 2*stride;
    const float* pa3 = pa + 3*stride;

    float sa = 0.f;

    for (int t = 0; t < TT; t += 2) {
        scan_step<0,1>(t,   S, RB, DB, KB, BF, AB, VB, sa,
                       pr2, pd2, pk2, pb2, pv2, pa3, py, stride, q);
        scan_step<1,0>(t+1, S, RB, DB, KB, BF, AB, VB, sa,
                       pr2, pd2, pk2, pb2, pv2, pa3, py, stride, q);
    }
}

// ---------------------------------------------------------------------------
// Kernel: combine — gate-mix fwd/bwd, groupnorm, residual, * g
// ---------------------------------------------------------------------------
__global__ void combine_kernel(const float* __restrict__ r_k,
                               const float* __restrict__ ln_g,
                               const float* __restrict__ ln_b)
{
    int bt = blockIdx.x;
    int tid = threadIdx.x;
    int c = tid * 4;
    int h = tid >> 4;
    size_t base = (size_t)bt * CC + c;

    float4 yf = *(const float4*)(g_yf + base);
    float4 yb = *(const float4*)(g_yb + base);
    float gate = g_gate[bt * HH + h];

    float4 xo;
    xo.x = gate * yf.x + (1.f - gate) * yb.x;
    xo.y = gate * yf.y + (1.f - gate) * yb.y;
    xo.z = gate * yf.z + (1.f - gate) * yb.z;
    xo.w = gate * yf.w + (1.f - gate) * yb.w;

    float4 rv = *(const float4*)(g_r + base);
    float4 kp = *(const float4*)(g_kp + base);
    float4 vv = *(const float4*)(g_v + base);
    float4 gv = *(const float4*)(g_g + base);
    float4 rk = *(const float4*)(r_k + c);

    float sum = xo.x + xo.y + xo.z + xo.w;
    float sq  = xo.x*xo.x + xo.y*xo.y + xo.z*xo.z + xo.w*xo.w;
    float sres = rv.x*kp.x*rk.x + rv.y*kp.y*rk.y + rv.z*kp.z*rk.z + rv.w*kp.w*rk.w;
    #pragma unroll
    for (int o = 1; o < 16; o <<= 1) {
        sum  += __shfl_xor_sync(0xffffffffu, sum, o);
        sq   += __shfl_xor_sync(0xffffffffu, sq, o);
        sres += __shfl_xor_sync(0xffffffffu, sres, o);
    }
    float mu = sum * (1.f / 64.f);
    float var = sq * (1.f / 64.f) - mu * mu;
    float rstd = rsqrtf(var + 0.00064f);

    float4 lg = *(const float4*)(ln_g + c);
    float4 lb = *(const float4*)(ln_b + c);

    float4 z;
    z.x = ((xo.x - mu) * rstd * lg.x + lb.x + sres * vv.x) * gv.x;
    z.y = ((xo.y - mu) * rstd * lg.y + lb.y + sres * vv.y) * gv.y;
    z.z = ((xo.z - mu) * rstd * lg.z + lb.z + sres * vv.z) * gv.z;
    z.w = ((xo.w - mu) * rstd * lg.w + lb.w + sres * vv.w) * gv.w;
    *(float4*)(g_z + base) = z;
}

// ---------------------------------------------------------------------------
// Host launcher
// ---------------------------------------------------------------------------
static float *P_xr, *P_xw, *P_xk, *P_xv, *P_xa, *P_xg;
static float *P_r, *P_k, *P_vraw;
static float *P_hw, *P_ha, *P_hv, *P_hg;
static float *P_dec, *P_a, *P_v, *P_g;
static float *P_z;
static bool s_init = false;

extern "C" void kernel_launch(void* const* d_in, const int* in_sizes, int n_in,
                              void* d_out, int out_size)
{
    const float* x       = (const float*)d_in[0];
    const float* v_first = (const float*)d_in[1];
    const float* x_r = (const float*)d_in[2];
    const float* x_w = (const float*)d_in[3];
    const float* x_k = (const float*)d_in[4];
    const float* x_v = (const float*)d_in[5];
    const float* x_a = (const float*)d_in[6];
    const float* x_g = (const float*)d_in[7];
    const float* w0  = (const float*)d_in[8];
    const float* w1  = (const float*)d_in[9];
    const float* w2  = (const float*)d_in[10];
    const float* a0  = (const float*)d_in[11];
    const float* a1  = (const float*)d_in[12];
    const float* a2  = (const float*)d_in[13];
    const float* v0  = (const float*)d_in[14];
    const float* v1  = (const float*)d_in[15];
    const float* v2  = (const float*)d_in[16];
    const float* g1  = (const float*)d_in[17];
    const float* g2  = (const float*)d_in[18];
    const float* k_k = (const float*)d_in[19];
    const float* k_a = (const float*)d_in[20];
    const float* r_k = (const float*)d_in[21];
    const float* gate_w = (const float*)d_in[22];
    const float* ln_g = (const float*)d_in[23];
    const float* ln_b = (const float*)d_in[24];
    const float* Wr = (const float*)d_in[25];
    const float* Wk = (const float*)d_in[26];
    const float* Wv = (const float*)d_in[27];
    const float* Wo = (const float*)d_in[28];
    float* out = (float*)d_out;

    if (!s_init) {
        cudaGetSymbolAddress((void**)&P_xr, g_xr);
        cudaGetSymbolAddress((void**)&P_xw, g_xw);
        cudaGetSymbolAddress((void**)&P_xk, g_xk);
        cudaGetSymbolAddress((void**)&P_xv, g_xv);
        cudaGetSymbolAddress((void**)&P_xa, g_xa);
        cudaGetSymbolAddress((void**)&P_xg, g_xg);
        cudaGetSymbolAddress((void**)&P_r, g_r);
        cudaGetSymbolAddress((void**)&P_k, g_k);
        cudaGetSymbolAddress((void**)&P_vraw, g_vraw);
        cudaGetSymbolAddress((void**)&P_hw, g_hw);
        cudaGetSymbolAddress((void**)&P_ha, g_ha);
        cudaGetSymbolAddress((void**)&P_hv, g_hv);
        cudaGetSymbolAddress((void**)&P_hg, g_hg);
        cudaGetSymbolAddress((void**)&P_dec, g_dec);
        cudaGetSymbolAddress((void**)&P_a, g_a);
        cudaGetSymbolAddress((void**)&P_v, g_v);
        cudaGetSymbolAddress((void**)&P_g, g_g);
        cudaGetSymbolAddress((void**)&P_z, g_z);
        s_init = true;
    }

    // 1) token shift + mixes + gate
    prep_kernel<<<BT, 128>>>(x, x_r, x_w, x_k, x_v, x_a, x_g, gate_w);

    // 2) big QKV GEMMs (A @ W^T), one launch
    {
        GemmJobs J = {};
        J.count = 3;
        J.tileStart[0] = 0; J.tileStart[1] = 8; J.tileStart[2] = 16; J.tileStart[3] = 24; J.tileStart[4] = 24;
        const float* As_[3] = { P_xr, P_xk, P_xv };
        const float* Bs_[3] = { Wr, Wk, Wv };
        float* Cs_[3] = { P_r, P_k, P_vraw };
        for (int jj = 0; jj < 3; jj++) {
            J.A[jj] = As_[jj]; J.Bm[jj] = Bs_[jj]; J.Cm[jj] = Cs_[jj];
            J.N[jj] = 512; J.K[jj] = 512; J.transb[jj] = 1; J.act[jj] = 0;
            J.bias[jj] = nullptr; J.aux1[jj] = nullptr; J.aux2[jj] = nullptr;
        }
        gemm_multi<<<dim3(24, 32), 256>>>(J);
    }

    // 3) stage-1 hidden GEMMs (A @ B), one launch
    {
        GemmJobs J = {};
        J.count = 4;
        J.tileStart[0] = 0; J.tileStart[1] = 1; J.tileStart[2] = 2; J.tileStart[3] = 3; J.tileStart[4] = 5;
        J.A[0] = P_xw; J.Bm[0] = w1; J.Cm[0] = P_hw; J.N[0] = 64;  J.K[0] = 512; J.transb[0] = 0; J.act[0] = 1;
        J.A[1] = P_xa; J.Bm[1] = a1; J.Cm[1] = P_ha; J.N[1] = 64;  J.K[1] = 512; J.transb[1] = 0; J.act[1] = 0;
        J.A[2] = x;    J.Bm[2] = v1; J.Cm[2] = P_hv; J.N[2] = 32;  J.K[2] = 512; J.transb[2] = 0; J.act[2] = 0;
        J.A[3] = P_xg; J.Bm[3] = g1; J.Cm[3] = P_hg; J.N[3] = 128; J.K[3] = 512; J.transb[3] = 0; J.act[3] = 2;
        for (int jj = 0; jj < 4; jj++) { J.bias[jj] = nullptr; J.aux1[jj] = nullptr; J.aux2[jj] = nullptr; }
        gemm_multi<<<dim3(5, 32), 256>>>(J);
    }

    // 4) stage-2 GEMMs with fused epilogues, one launch
    {
        GemmJobs J = {};
        J.count = 4;
        J.tileStart[0] = 0; J.tileStart[1] = 8; J.tileStart[2] = 16; J.tileStart[3] = 24; J.tileStart[4] = 32;
        J.A[0] = P_hw; J.Bm[0] = w2; J.Cm[0] = P_dec; J.N[0] = 512; J.K[0] = 64;  J.transb[0] = 0; J.act[0] = 3;
        J.bias[0] = w0; J.aux1[0] = nullptr; J.aux2[0] = nullptr;
        J.A[1] = P_ha; J.Bm[1] = a2; J.Cm[1] = P_a; J.N[1] = 512; J.K[1] = 64;  J.transb[1] = 0; J.act[1] = 2;
        J.bias[1] = a0; J.aux1[1] = nullptr; J.aux2[1] = nullptr;
        J.A[2] = P_hv; J.Bm[2] = v2; J.Cm[2] = P_v; J.N[2] = 512; J.K[2] = 32;  J.transb[2] = 0; J.act[2] = 4;
        J.bias[2] = v0; J.aux1[2] = P_vraw; J.aux2[2] = v_first;
        J.A[3] = P_hg; J.Bm[3] = g2; J.Cm[3] = P_g; J.N[3] = 512; J.K[3] = 128; J.transb[3] = 0; J.act[3] = 0;
        J.bias[3] = nullptr; J.aux1[3] = nullptr; J.aux2[3] = nullptr;
        gemm_multi<<<dim3(32, 32), 256>>>(J);
    }

    // 5) kk normalize, k', aa, bb
    post_kernel<<<BT, 128>>>(k_k, k_a);

    // 6) bidirectional WKV7 scan — 128 blocks x 256 threads, no spills
    scan_kernel<<<128, 256>>>();

    // 7) combine + groupnorm + residual + *g
    combine_kernel<<<BT, 128>>>(r_k, ln_g, ln_b);

    // 8) out = z @ Wo^T
    {
        GemmJobs J = {};
        J.count = 1;
        J.tileStart[0] = 0; J.tileStart[1] = 8; J.tileStart[2] = 8; J.tileStart[3] = 8; J.tileStart[4] = 8;
        J.A[0] = P_z; J.Bm[0] = Wo; J.Cm[0] = out;
        J.N[0] = 512; J.K[0] = 512; J.transb[0] = 1; J.act[0] = 0;
        J.bias[0] = nullptr; J.aux1[0] = nullptr; J.aux2[0] = nullptr;
        gemm_multi<<<dim3(8, 32), 256>>>(J);
    }

    // 9) v_first passthrough if the flattened output includes it
    if (out_size >= 2 * BTC) {
        cudaMemcpyAsync(out + BTC, v_first, (size_t)BTC * sizeof(float),
                        cudaMemcpyDeviceToDevice, 0);
    }
}

// round 5
// speedup vs baseline: 1.5978x; 1.0547x over previous
#include <cuda_runtime.h>
#include <cstdint>
#include <math.h>

// Problem sizes (fixed)
#define BB   4
#define TT   1024
#define CC   512
#define HH   8
#define NN   64
#define BT   (BB*TT)        // 4096
#define BTC  (BT*CC)        // 2097152

// ---------------------------------------------------------------------------
// Workspace (static __device__ arrays; no allocation at runtime)
// ---------------------------------------------------------------------------
__device__ float g_xr[BTC], g_xw[BTC], g_xk[BTC], g_xv[BTC], g_xa[BTC], g_xg[BTC];
__device__ float g_gate[BT*HH];
__device__ float g_r[BTC], g_k[BTC], g_vraw[BTC];
__device__ float g_hw[BT*64], g_ha[BT*64], g_hv[BT*32], g_hg[BT*128];
__device__ float g_dec[BTC], g_a[BTC], g_v[BTC], g_g[BTC];
__device__ float g_kp[BTC], g_aa[BTC], g_bb[BTC];
__device__ float g_yf[BTC], g_yb[BTC], g_z[BTC];

// ---------------------------------------------------------------------------
// Kernel 1: token shift, six mixes, per-head gate
// ---------------------------------------------------------------------------
__global__ void prep_kernel(const float* __restrict__ x,
                            const float* __restrict__ mr, const float* __restrict__ mw,
                            const float* __restrict__ mk, const float* __restrict__ mv,
                            const float* __restrict__ ma, const float* __restrict__ mg,
                            const float* __restrict__ gate_w)
{
    int bt = blockIdx.x;
    int t  = bt & (TT - 1);
    int tid = threadIdx.x;
    int c  = tid * 4;
    size_t base = (size_t)bt * CC + c;

    float4 xc = *(const float4*)(x + base);
    float4 xp = make_float4(0.f, 0.f, 0.f, 0.f);
    if (t != 0) xp = *(const float4*)(x + base - CC);

    float4 xx;
    xx.x = xp.x - xc.x; xx.y = xp.y - xc.y; xx.z = xp.z - xc.z; xx.w = xp.w - xc.w;

#define MIXOUT(dst, mvptr)                                                    \
    { float4 m = *(const float4*)(mvptr + c); float4 o;                       \
      o.x = xc.x + xx.x * m.x; o.y = xc.y + xx.y * m.y;                       \
      o.z = xc.z + xx.z * m.z; o.w = xc.w + xx.w * m.w;                       \
      *(float4*)(dst + base) = o; }
    MIXOUT(g_xr, mr); MIXOUT(g_xw, mw); MIXOUT(g_xk, mk);
    MIXOUT(g_xv, mv); MIXOUT(g_xa, ma); MIXOUT(g_xg, mg);
#undef MIXOUT

    float4 gw = *(const float4*)(gate_w + c);
    float p = xx.x*gw.x + xx.y*gw.y + xx.z*gw.z + xx.w*gw.w;
    #pragma unroll
    for (int o = 1; o < 16; o <<= 1) p += __shfl_xor_sync(0xffffffffu, p, o);
    if ((tid & 15) == 0)
        g_gate[bt*HH + (tid >> 4)] = 1.f / (1.f + expf(-p));
}

// ---------------------------------------------------------------------------
// tf32 tensor-core GEMM: C[4096,512] = A[4096,512] @ W^T (W is [512,512] row-major)
// Block tile 128x64, 8 warps (4m x 2n), warp tile 32x32, K staged 32 at a time.
// mma.sync.aligned.m16n8k8.row.col.f32.tf32.tf32.f32
// ---------------------------------------------------------------------------
struct QkvJobs {
    const float* A[3];
    const float* W[3];
    float*       C[3];
};

__device__ __forceinline__ uint32_t f2tf32(float x) {
    uint32_t r;
    asm("cvt.rna.tf32.f32 %0, %1;" : "=r"(r) : "f"(x));
    return r;
}

__device__ __forceinline__ void mma_tf32(float* d, const uint32_t* a, const uint32_t* b) {
    asm("mma.sync.aligned.m16n8k8.row.col.f32.tf32.tf32.f32 "
        "{%0,%1,%2,%3},{%4,%5,%6,%7},{%8,%9},{%0,%1,%2,%3};"
        : "+f"(d[0]), "+f"(d[1]), "+f"(d[2]), "+f"(d[3])
        : "r"(a[0]), "r"(a[1]), "r"(a[2]), "r"(a[3]), "r"(b[0]), "r"(b[1]));
}

__global__ __launch_bounds__(256, 2) void gemm_tf32_nt(QkvJobs J)
{
    const int K = 512, N = 512;
    const float* A = J.A[blockIdx.z];
    const float* W = J.W[blockIdx.z];
    float*       C = J.C[blockIdx.z];

    int m0 = blockIdx.y * 128;
    int n0 = blockIdx.x * 64;

    __shared__ uint32_t As[32][132];
    __shared__ uint32_t Bs[32][68];

    int tid  = threadIdx.x;
    int warp = tid >> 5, lane = tid & 31;
    int g = lane >> 2, c = lane & 3;
    int wm = warp & 3, wn = warp >> 2;

    float acc[2][4][4];
    #pragma unroll
    for (int mt = 0; mt < 2; mt++)
        #pragma unroll
        for (int nt = 0; nt < 4; nt++)
            #pragma unroll
            for (int r = 0; r < 4; r++) acc[mt][nt][r] = 0.f;

    for (int k0 = 0; k0 < K; k0 += 32) {
        // A tile 128x32 -> As[k][m] (tf32-converted)
        #pragma unroll
        for (int it = 0; it < 4; it++) {
            int idx = tid + it * 256;
            int m = idx >> 3, kc = (idx & 7) * 4;
            float4 v = *(const float4*)(A + (size_t)(m0 + m) * K + k0 + kc);
            As[kc+0][m] = f2tf32(v.x);
            As[kc+1][m] = f2tf32(v.y);
            As[kc+2][m] = f2tf32(v.z);
            As[kc+3][m] = f2tf32(v.w);
        }
        // B tile 64x32 from W[n][k] -> Bs[k][n]
        #pragma unroll
        for (int it = 0; it < 2; it++) {
            int idx = tid + it * 256;
            int n = idx >> 3, kc = (idx & 7) * 4;
            float4 v = *(const float4*)(W + (size_t)(n0 + n) * K + k0 + kc);
            Bs[kc+0][n] = f2tf32(v.x);
            Bs[kc+1][n] = f2tf32(v.y);
            Bs[kc+2][n] = f2tf32(v.z);
            Bs[kc+3][n] = f2tf32(v.w);
        }
        __syncthreads();

        #pragma unroll
        for (int k8 = 0; k8 < 4; k8++) {
            int kr = k8 * 8;
            uint32_t a[2][4], b[4][2];
            #pragma unroll
            for (int mt = 0; mt < 2; mt++) {
                int mb = wm * 32 + mt * 16;
                a[mt][0] = As[kr + c    ][mb + g    ];
                a[mt][1] = As[kr + c    ][mb + g + 8];
                a[mt][2] = As[kr + c + 4][mb + g    ];
                a[mt][3] = As[kr + c + 4][mb + g + 8];
            }
            #pragma unroll
            for (int nt = 0; nt < 4; nt++) {
                int nb = wn * 32 + nt * 8;
                b[nt][0] = Bs[kr + c    ][nb + g];
                b[nt][1] = Bs[kr + c + 4][nb + g];
            }
            #pragma unroll
            for (int mt = 0; mt < 2; mt++)
                #pragma unroll
                for (int nt = 0; nt < 4; nt++)
                    mma_tf32(acc[mt][nt], a[mt], b[nt]);
        }
        __syncthreads();
    }

    // epilogue: c0,c1 at (row, 2c), c2,c3 at (row+8, 2c)
    #pragma unroll
    for (int mt = 0; mt < 2; mt++) {
        int row = m0 + wm * 32 + mt * 16 + g;
        #pragma unroll
        for (int nt = 0; nt < 4; nt++) {
            int col = n0 + wn * 32 + nt * 8 + 2 * c;
            float2 v0 = make_float2(acc[mt][nt][0], acc[mt][nt][1]);
            float2 v1 = make_float2(acc[mt][nt][2], acc[mt][nt][3]);
            *(float2*)(C + (size_t)row * N + col)       = v0;
            *(float2*)(C + (size_t)(row + 8) * N + col) = v1;
        }
    }
}

// ---------------------------------------------------------------------------
// Generic multi-job FFMA SGEMM (kept for stage-1/2 MLPs: decay path stays fp32)
// ---------------------------------------------------------------------------
#define GBM 128
#define GBN 64
#define GBK 16

struct GemmJobs {
    int count;
    int tileStart[5];
    const float* A[4];
    const float* Bm[4];
    float*       Cm[4];
    int N[4];
    int K[4];
    int transb[4];
    int act[4];
    const float* bias[4];
    const float* aux1[4];
    const float* aux2[4];
};

__global__ __launch_bounds__(256, 2) void gemm_multi(GemmJobs J)
{
    __shared__ __align__(16) float As[GBK][GBM + 4];
    __shared__ __align__(16) float Bs[GBK][GBN + 4];

    int bx = blockIdx.x;
    int j = 0;
    while (bx >= J.tileStart[j + 1]) ++j;
    int n0 = (bx - J.tileStart[j]) * GBN;
    int m0 = blockIdx.y * GBM;

    const float* A = J.A[j];
    const float* B = J.Bm[j];
    float*       C = J.Cm[j];
    const int N = J.N[j];
    const int K = J.K[j];
    const int tb = J.transb[j];

    int tid = threadIdx.x;
    int tx = tid & 15, ty = tid >> 4;

    float acc[8][4];
    #pragma unroll
    for (int im = 0; im < 8; im++)
        #pragma unroll
        for (int in = 0; in < 4; in++) acc[im][in] = 0.f;

    for (int k0 = 0; k0 < K; k0 += GBK) {
        #pragma unroll
        for (int it = 0; it < 2; it++) {
            int lid = tid + it * 256;
            int row = lid >> 2, kc = lid & 3;
            float4 v = *(const float4*)(A + (size_t)(m0 + row) * K + k0 + kc * 4);
            As[kc*4+0][row] = v.x;
            As[kc*4+1][row] = v.y;
            As[kc*4+2][row] = v.z;
            As[kc*4+3][row] = v.w;
        }
        if (tb) {
            int row = tid >> 2, kc = tid & 3;
            float4 v = *(const float4*)(B + (size_t)(n0 + row) * K + k0 + kc * 4);
            Bs[kc*4+0][row] = v.x;
            Bs[kc*4+1][row] = v.y;
            Bs[kc*4+2][row] = v.z;
            Bs[kc*4+3][row] = v.w;
        } else {
            int kr = tid >> 4, c4 = (tid & 15) * 4;
            float4 v = make_float4(0.f, 0.f, 0.f, 0.f);
            if (n0 + c4 < N)
                v = *(const float4*)(B + (size_t)(k0 + kr) * N + n0 + c4);
            *(float4*)&Bs[kr][c4] = v;
        }
        __syncthreads();

        #pragma unroll
        for (int kk = 0; kk < GBK; kk++) {
            float4 bf = *(const float4*)&Bs[kk][tx * 4];
            float4 a0 = *(const float4*)&As[kk][ty * 8];
            float4 a1 = *(const float4*)&As[kk][ty * 8 + 4];
            float af[8] = {a0.x, a0.y, a0.z, a0.w, a1.x, a1.y, a1.z, a1.w};
            float bb2[4] = {bf.x, bf.y, bf.z, bf.w};
            #pragma unroll
            for (int im = 0; im < 8; im++)
                #pragma unroll
                for (int in = 0; in < 4; in++) acc[im][in] += af[im] * bb2[in];
        }
        __syncthreads();
    }

    const int act = J.act[j];
    const float* bias = J.bias[j];
    const float* aux1 = J.aux1[j];
    const float* aux2 = J.aux2[j];

    #pragma unroll
    for (int im = 0; im < 8; im++) {
        int row = m0 + ty * 8 + im;
        #pragma unroll
        for (int in = 0; in < 4; in++) {
            int col = n0 + tx * 4 + in;
            if (col < N) {
                size_t idx = (size_t)row * N + col;
                float v = acc[im][in];
                float o;
                if (act == 0) {
                    o = v;
                } else if (act == 1) {
                    o = tanhf(v);
                } else if (act == 2) {
                    float z = v + (bias ? bias[col] : 0.f);
                    o = 1.f / (1.f + expf(-z));
                } else if (act == 3) {
                    float z = v + bias[col];
                    float s = 1.f / (1.f + expf(-z));
                    o = expf(-0.60653065971263342f * s);
                } else {
                    float z = v + bias[col];
                    float s = 1.f / (1.f + expf(-z));
                    float vr = aux1[idx];
                    o = vr + (aux2[idx] - vr) * s;
                }
                C[idx] = o;
            }
        }
    }
}

// ---------------------------------------------------------------------------
// Kernel: post — kk normalization per head, k' update, aa=-kk, bb=kk*a
// ---------------------------------------------------------------------------
__global__ void post_kernel(const float* __restrict__ k_k, const float* __restrict__ k_a)
{
    int bt = blockIdx.x;
    int tid = threadIdx.x;
    int c = tid * 4;
    size_t base = (size_t)bt * CC + c;

    float4 kv = *(const float4*)(g_k + base);
    float4 av = *(const float4*)(g_a + base);
    float4 kkc = *(const float4*)(k_k + c);
    float4 kac = *(const float4*)(k_a + c);

    float4 kk;
    kk.x = kv.x * kkc.x; kk.y = kv.y * kkc.y; kk.z = kv.z * kkc.z; kk.w = kv.w * kkc.w;
    float ss = kk.x*kk.x + kk.y*kk.y + kk.z*kk.z + kk.w*kk.w;
    #pragma unroll
    for (int o = 1; o < 16; o <<= 1) ss += __shfl_xor_sync(0xffffffffu, ss, o);

    float nrm = sqrtf(ss);
    float inv = 1.f / fmaxf(nrm, 1e-12f);

    float4 aa, bb, kp;
    aa.x = -kk.x * inv; aa.y = -kk.y * inv; aa.z = -kk.z * inv; aa.w = -kk.w * inv;
    bb.x = kk.x * inv * av.x; bb.y = kk.y * inv * av.y;
    bb.z = kk.z * inv * av.z; bb.w = kk.w * inv * av.w;
    kp.x = kv.x * (1.f + (av.x - 1.f) * kac.x);
    kp.y = kv.y * (1.f + (av.y - 1.f) * kac.y);
    kp.z = kv.z * (1.f + (av.z - 1.f) * kac.z);
    kp.w = kv.w * (1.f + (av.w - 1.f) * kac.w);

    *(float4*)(g_aa + base) = aa;
    *(float4*)(g_bb + base) = bb;
    *(float4*)(g_kp + base) = kp;
}

// ---------------------------------------------------------------------------
// Kernel: bidirectional WKV7 scan — 8 cols/thread, 256 thr/block (unchanged)
// ---------------------------------------------------------------------------
template<int CS, int NS>
__device__ __forceinline__ void scan_step(
    int T, float (&S)[8],
    float (&RB)[2][8], float (&DB)[2][8], float (&KB)[2][8],
    float (&BF)[2][8], float (&AB)[2][8], float (&VB)[2],
    float& sa,
    const float*& pr2, const float*& pd2, const float*& pk2,
    const float*& pb2, const float*& pv2, const float*& pa3,
    float*& py, int stride, int q)
{
    float y0 = 0.f, y1 = 0.f;
    float z0 = 0.f, z1 = 0.f;
    float Vv = VB[CS];
    #pragma unroll
    for (int j = 0; j < 4; j++) {
        float sj;
        sj = S[j]   * DB[CS][j]   + sa * BF[CS][j]   + Vv * KB[CS][j];
        S[j] = sj;    y0 += sj * RB[CS][j];    z0 += sj * AB[NS][j];
        sj = S[4+j] * DB[CS][4+j] + sa * BF[CS][4+j] + Vv * KB[CS][4+j];
        S[4+j] = sj;  y1 += sj * RB[CS][4+j];  z1 += sj * AB[NS][4+j];
    }
    float y   = y0 + y1;
    float sap = z0 + z1;

    if (T + 2 < TT) {
        #pragma unroll
        for (int u = 0; u < 2; u++) {
            *(float4*)&RB[CS][u*4] = *(const float4*)(pr2 + u*4);
            *(float4*)&DB[CS][u*4] = *(const float4*)(pd2 + u*4);
            *(float4*)&KB[CS][u*4] = *(const float4*)(pk2 + u*4);
            *(float4*)&BF[CS][u*4] = *(const float4*)(pb2 + u*4);
        }
        VB[CS] = *pv2;
    }
    pr2 += stride; pd2 += stride; pk2 += stride; pb2 += stride; pv2 += stride;
    if (T + 3 < TT) {
        #pragma unroll
        for (int u = 0; u < 2; u++)
            *(float4*)&AB[NS][u*4] = *(const float4*)(pa3 + u*4);
    }
    pa3 += stride;

    y   += __shfl_xor_sync(0xffffffffu, y, 1);
    sap += __shfl_xor_sync(0xffffffffu, sap, 1);
    y   += __shfl_xor_sync(0xffffffffu, y, 2);
    sap += __shfl_xor_sync(0xffffffffu, sap, 2);
    y   += __shfl_xor_sync(0xffffffffu, y, 4);
    sap += __shfl_xor_sync(0xffffffffu, sap, 4);

    if (q == 0) *py = y;
    py += stride;
    sa = sap;
}

__global__ __launch_bounds__(256, 1) void scan_kernel()
{
    int bx = blockIdx.x;
    int dir = bx >> 6;
    int b   = (bx >> 4) & 3;
    int h   = (bx >> 1) & 7;
    int rg  = bx & 1;
    int tid = threadIdx.x;
    int i   = rg * 32 + (tid >> 3);
    int q   = tid & 7;
    int c0  = q * 8;

    int t0 = dir ? (TT - 1) : 0;
    int stride = dir ? -CC : CC;
    size_t off = (size_t)(b * TT + t0) * CC + h * NN;

    const float* pr = g_r   + off + c0;
    const float* pd = g_dec + off + c0;
    const float* pk = g_kp  + off + c0;
    const float* pa = g_aa  + off + c0;
    const float* pb = g_bb  + off + c0;
    const float* pv = g_v   + off + i;
    float* py = (dir ? g_yb : g_yf) + off + i;

    float S[8];
    #pragma unroll
    for (int j = 0; j < 8; j++) S[j] = 0.f;

    float RB[2][8], DB[2][8], KB[2][8], BF[2][8], AB[2][8], VB[2];

    #pragma unroll
    for (int u = 0; u < 2; u++) {
        *(float4*)&RB[0][u*4] = *(const float4*)(pr + u*4);
        *(float4*)&DB[0][u*4] = *(const float4*)(pd + u*4);
        *(float4*)&KB[0][u*4] = *(const float4*)(pk + u*4);
        *(float4*)&BF[0][u*4] = *(const float4*)(pb + u*4);
        *(float4*)&RB[1][u*4] = *(const float4*)(pr + stride + u*4);
        *(float4*)&DB[1][u*4] = *(const float4*)(pd + stride + u*4);
        *(float4*)&KB[1][u*4] = *(const float4*)(pk + stride + u*4);
        *(float4*)&BF[1][u*4] = *(const float4*)(pb + stride + u*4);
        *(float4*)&AB[1][u*4] = *(const float4*)(pa + stride + u*4);
        *(float4*)&AB[0][u*4] = *(const float4*)(pa + 2*stride + u*4);
    }
    VB[0] = *pv;
    VB[1] = *(pv + stride);

    const float* pr2 = pr + 2*stride;
    const float* pd2 = pd + 2*stride;
    const float* pk2 = pk + 2*stride;
    const float* pb2 = pb + 2*stride;
    const float* pv2 = pv + 2*stride;
    const float* pa3 = pa + 3*stride;

    float sa = 0.f;

    for (int t = 0; t < TT; t += 2) {
        scan_step<0,1>(t,   S, RB, DB, KB, BF, AB, VB, sa,
                       pr2, pd2, pk2, pb2, pv2, pa3, py, stride, q);
        scan_step<1,0>(t+1, S, RB, DB, KB, BF, AB, VB, sa,
                       pr2, pd2, pk2, pb2, pv2, pa3, py, stride, q);
    }
}

// ---------------------------------------------------------------------------
// Kernel: combine — gate-mix fwd/bwd, groupnorm, residual, * g
// ---------------------------------------------------------------------------
__global__ void combine_kernel(const float* __restrict__ r_k,
                               const float* __restrict__ ln_g,
                               const float* __restrict__ ln_b)
{
    int bt = blockIdx.x;
    int tid = threadIdx.x;
    int c = tid * 4;
    int h = tid >> 4;
    size_t base = (size_t)bt * CC + c;

    float4 yf = *(const float4*)(g_yf + base);
    float4 yb = *(const float4*)(g_yb + base);
    float gate = g_gate[bt * HH + h];

    float4 xo;
    xo.x = gate * yf.x + (1.f - gate) * yb.x;
    xo.y = gate * yf.y + (1.f - gate) * yb.y;
    xo.z = gate * yf.z + (1.f - gate) * yb.z;
    xo.w = gate * yf.w + (1.f - gate) * yb.w;

    float4 rv = *(const float4*)(g_r + base);
    float4 kp = *(const float4*)(g_kp + base);
    float4 vv = *(const float4*)(g_v + base);
    float4 gv = *(const float4*)(g_g + base);
    float4 rk = *(const float4*)(r_k + c);

    float sum = xo.x + xo.y + xo.z + xo.w;
    float sq  = xo.x*xo.x + xo.y*xo.y + xo.z*xo.z + xo.w*xo.w;
    float sres = rv.x*kp.x*rk.x + rv.y*kp.y*rk.y + rv.z*kp.z*rk.z + rv.w*kp.w*rk.w;
    #pragma unroll
    for (int o = 1; o < 16; o <<= 1) {
        sum  += __shfl_xor_sync(0xffffffffu, sum, o);
        sq   += __shfl_xor_sync(0xffffffffu, sq, o);
        sres += __shfl_xor_sync(0xffffffffu, sres, o);
    }
    float mu = sum * (1.f / 64.f);
    float var = sq * (1.f / 64.f) - mu * mu;
    float rstd = rsqrtf(var + 0.00064f);

    float4 lg = *(const float4*)(ln_g + c);
    float4 lb = *(const float4*)(ln_b + c);

    float4 z;
    z.x = ((xo.x - mu) * rstd * lg.x + lb.x + sres * vv.x) * gv.x;
    z.y = ((xo.y - mu) * rstd * lg.y + lb.y + sres * vv.y) * gv.y;
    z.z = ((xo.z - mu) * rstd * lg.z + lb.z + sres * vv.z) * gv.z;
    z.w = ((xo.w - mu) * rstd * lg.w + lb.w + sres * vv.w) * gv.w;
    *(float4*)(g_z + base) = z;
}

// ---------------------------------------------------------------------------
// Host launcher
// ---------------------------------------------------------------------------
static float *P_xr, *P_xw, *P_xk, *P_xv, *P_xa, *P_xg;
static float *P_r, *P_k, *P_vraw;
static float *P_hw, *P_ha, *P_hv, *P_hg;
static float *P_dec, *P_a, *P_v, *P_g;
static float *P_z;
static bool s_init = false;

extern "C" void kernel_launch(void* const* d_in, const int* in_sizes, int n_in,
                              void* d_out, int out_size)
{
    const float* x       = (const float*)d_in[0];
    const float* v_first = (const float*)d_in[1];
    const float* x_r = (const float*)d_in[2];
    const float* x_w = (const float*)d_in[3];
    const float* x_k = (const float*)d_in[4];
    const float* x_v = (const float*)d_in[5];
    const float* x_a = (const float*)d_in[6];
    const float* x_g = (const float*)d_in[7];
    const float* w0  = (const float*)d_in[8];
    const float* w1  = (const float*)d_in[9];
    const float* w2  = (const float*)d_in[10];
    const float* a0  = (const float*)d_in[11];
    const float* a1  = (const float*)d_in[12];
    const float* a2  = (const float*)d_in[13];
    const float* v0  = (const float*)d_in[14];
    const float* v1  = (const float*)d_in[15];
    const float* v2  = (const float*)d_in[16];
    const float* g1  = (const float*)d_in[17];
    const float* g2  = (const float*)d_in[18];
    const float* k_k = (const float*)d_in[19];
    const float* k_a = (const float*)d_in[20];
    const float* r_k = (const float*)d_in[21];
    const float* gate_w = (const float*)d_in[22];
    const float* ln_g = (const float*)d_in[23];
    const float* ln_b = (const float*)d_in[24];
    const float* Wr = (const float*)d_in[25];
    const float* Wk = (const float*)d_in[26];
    const float* Wv = (const float*)d_in[27];
    const float* Wo = (const float*)d_in[28];
    float* out = (float*)d_out;

    if (!s_init) {
        cudaGetSymbolAddress((void**)&P_xr, g_xr);
        cudaGetSymbolAddress((void**)&P_xw, g_xw);
        cudaGetSymbolAddress((void**)&P_xk, g_xk);
        cudaGetSymbolAddress((void**)&P_xv, g_xv);
        cudaGetSymbolAddress((void**)&P_xa, g_xa);
        cudaGetSymbolAddress((void**)&P_xg, g_xg);
        cudaGetSymbolAddress((void**)&P_r, g_r);
        cudaGetSymbolAddress((void**)&P_k, g_k);
        cudaGetSymbolAddress((void**)&P_vraw, g_vraw);
        cudaGetSymbolAddress((void**)&P_hw, g_hw);
        cudaGetSymbolAddress((void**)&P_ha, g_ha);
        cudaGetSymbolAddress((void**)&P_hv, g_hv);
        cudaGetSymbolAddress((void**)&P_hg, g_hg);
        cudaGetSymbolAddress((void**)&P_dec, g_dec);
        cudaGetSymbolAddress((void**)&P_a, g_a);
        cudaGetSymbolAddress((void**)&P_v, g_v);
        cudaGetSymbolAddress((void**)&P_g, g_g);
        cudaGetSymbolAddress((void**)&P_z, g_z);
        s_init = true;
    }

    // 1) token shift + mixes + gate
    prep_kernel<<<BT, 128>>>(x, x_r, x_w, x_k, x_v, x_a, x_g, gate_w);

    // 2) big QKV GEMMs — tf32 tensor cores, one launch
    {
        QkvJobs J;
        J.A[0] = P_xr; J.W[0] = Wr; J.C[0] = P_r;
        J.A[1] = P_xk; J.W[1] = Wk; J.C[1] = P_k;
        J.A[2] = P_xv; J.W[2] = Wv; J.C[2] = P_vraw;
        gemm_tf32_nt<<<dim3(8, 32, 3), 256>>>(J);
    }

    // 3) stage-1 hidden GEMMs (fp32 FFMA — decay path precision)
    {
        GemmJobs J = {};
        J.count = 4;
        J.tileStart[0] = 0; J.tileStart[1] = 1; J.tileStart[2] = 2; J.tileStart[3] = 3; J.tileStart[4] = 5;
        J.A[0] = P_xw; J.Bm[0] = w1; J.Cm[0] = P_hw; J.N[0] = 64;  J.K[0] = 512; J.transb[0] = 0; J.act[0] = 1;
        J.A[1] = P_xa; J.Bm[1] = a1; J.Cm[1] = P_ha; J.N[1] = 64;  J.K[1] = 512; J.transb[1] = 0; J.act[1] = 0;
        J.A[2] = x;    J.Bm[2] = v1; J.Cm[2] = P_hv; J.N[2] = 32;  J.K[2] = 512; J.transb[2] = 0; J.act[2] = 0;
        J.A[3] = P_xg; J.Bm[3] = g1; J.Cm[3] = P_hg; J.N[3] = 128; J.K[3] = 512; J.transb[3] = 0; J.act[3] = 2;
        for (int jj = 0; jj < 4; jj++) { J.bias[jj] = nullptr; J.aux1[jj] = nullptr; J.aux2[jj] = nullptr; }
        gemm_multi<<<dim3(5, 32), 256>>>(J);
    }

    // 4) stage-2 GEMMs with fused epilogues (fp32 FFMA)
    {
        GemmJobs J = {};
        J.count = 4;
        J.tileStart[0] = 0; J.tileStart[1] = 8; J.tileStart[2] = 16; J.tileStart[3] = 24; J.tileStart[4] = 32;
        J.A[0] = P_hw; J.Bm[0] = w2; J.Cm[0] = P_dec; J.N[0] = 512; J.K[0] = 64;  J.transb[0] = 0; J.act[0] = 3;
        J.bias[0] = w0; J.aux1[0] = nullptr; J.aux2[0] = nullptr;
        J.A[1] = P_ha; J.Bm[1] = a2; J.Cm[1] = P_a; J.N[1] = 512; J.K[1] = 64;  J.transb[1] = 0; J.act[1] = 2;
        J.bias[1] = a0; J.aux1[1] = nullptr; J.aux2[1] = nullptr;
        J.A[2] = P_hv; J.Bm[2] = v2; J.Cm[2] = P_v; J.N[2] = 512; J.K[2] = 32;  J.transb[2] = 0; J.act[2] = 4;
        J.bias[2] = v0; J.aux1[2] = P_vraw; J.aux2[2] = v_first;
        J.A[3] = P_hg; J.Bm[3] = g2; J.Cm[3] = P_g; J.N[3] = 512; J.K[3] = 128; J.transb[3] = 0; J.act[3] = 0;
        J.bias[3] = nullptr; J.aux1[3] = nullptr; J.aux2[3] = nullptr;
        gemm_multi<<<dim3(32, 32), 256>>>(J);
    }

    // 5) kk normalize, k', aa, bb
    post_kernel<<<BT, 128>>>(k_k, k_a);

    // 6) bidirectional WKV7 scan
    scan_kernel<<<128, 256>>>();

    // 7) combine + groupnorm + residual + *g
    combine_kernel<<<BT, 128>>>(r_k, ln_g, ln_b);

    // 8) out = z @ Wo^T — tf32 tensor cores
    {
        QkvJobs J;
        J.A[0] = P_z; J.W[0] = Wo; J.C[0] = out;
        J.A[1] = P_z; J.W[1] = Wo; J.C[1] = out;
        J.A[2] = P_z; J.W[2] = Wo; J.C[2] = out;
        gemm_tf32_nt<<<dim3(8, 32, 1), 256>>>(J);
    }

    // 9) v_first passthrough if the flattened output includes it
    if (out_size >= 2 * BTC) {
        cudaMemcpyAsync(out + BTC, v_first, (size_t)BTC * sizeof(float),
                        cudaMemcpyDeviceToDevice, 0);
    }
}